// round 13
// baseline (speedup 1.0000x reference)
#include <cuda_runtime.h>
#include <cuda_fp16.h>
#include <math.h>
#include <stdint.h>

#define F_INF __int_as_float(0x7f800000)

// Problem dims
#define Dm 768
#define Em 768
#define Hh 12
#define Bb 4
#define Ss 512
#define Vv 32000
#define Tt (Bb*Ss)   // 2048

// ---------------- scratch (device globals) ----------------------------------
__device__ __half g_x[Tt*Dm];              // embed+LN out
__device__ __half g_qkv[3*Hh*Tt*Em];       // [3][H][T][E]  (q,k,v slabs)
__device__ __half g_vT[Hh*Em*Tt];          // V transposed per head: [H][E][T]
__device__ __half g_sc[Bb*Hh*Ss*Ss];       // scores / attn
__device__ __half g_ctx[Tt*Hh*Em];
__device__ __half g_h1[Tt*Em];             // gelu intermediate
__device__ __half g_h2[Tt*Dm];             // LN(attn) out
__device__ __half g_enc[Tt*Dm];            // final LN out
__device__ float  g_f1[Tt*Dm];             // fp32 staging for LN inputs
__device__ __half g_logits[(size_t)Tt*Vv]; // fp16 logits staging
// packed transposed half weights
__device__ __half g_wqkvt[3*Hh*Em*Dm];     // [3][H][E][D]
__device__ float  g_bqkv[3*Hh*Em];         // packed fp32 biases
__device__ __half g_wot[Dm*Hh*Em];
__device__ __half g_w1t[Em*Dm];
__device__ __half g_w2t[Dm*Em];
__device__ __half g_wpt[Vv*Dm];

// ---------------- helpers ----------------
__device__ __forceinline__ float warpSum(float v){
    #pragma unroll
    for (int o=16;o;o>>=1) v += __shfl_xor_sync(0xffffffffu, v, o);
    return v;
}
__device__ __forceinline__ float warpMax(float v){
    #pragma unroll
    for (int o=16;o;o>>=1) v = fmaxf(v, __shfl_xor_sync(0xffffffffu, v, o));
    return v;
}
__device__ float blockSum(float v){
    __shared__ float sh[33];
    int lane = threadIdx.x & 31, wid = threadIdx.x >> 5;
    v = warpSum(v);
    __syncthreads();
    if (lane==0) sh[wid] = v;
    __syncthreads();
    if (wid==0){
        int nw = blockDim.x >> 5;
        float t = (lane < nw) ? sh[lane] : 0.f;
        t = warpSum(t);
        if (lane==0) sh[32] = t;
    }
    __syncthreads();
    return sh[32];
}
__device__ float blockMax(float v){
    __shared__ float sh[33];
    int lane = threadIdx.x & 31, wid = threadIdx.x >> 5;
    v = warpMax(v);
    __syncthreads();
    if (lane==0) sh[wid] = v;
    __syncthreads();
    if (wid==0){
        int nw = blockDim.x >> 5;
        float t = (lane < nw) ? sh[lane] : -F_INF;
        t = warpMax(t);
        if (lane==0) sh[32] = t;
    }
    __syncthreads();
    return sh[32];
}

// ---------------- transpose: src[R][C] -> dst[C][R] (to half) ---------------
template<typename TI>
__global__ void transpose_h_kernel(const TI* __restrict__ src,
                                   __half* __restrict__ dst,
                                   int R, int C)
{
    __shared__ float tile[32][33];
    int z = blockIdx.z;
    src += (size_t)z*R*C;
    dst += (size_t)z*R*C;
    int c0 = blockIdx.x*32, r0 = blockIdx.y*32;
    int tx = threadIdx.x, ty = threadIdx.y;     // 32 x 8
    #pragma unroll
    for (int i=0;i<32;i+=8)
        tile[ty+i][tx] = (float)src[(size_t)(r0+ty+i)*C + c0+tx];
    __syncthreads();
    #pragma unroll
    for (int i=0;i<32;i+=8)
        dst[(size_t)(c0+ty+i)*R + r0+tx] = __float2half(tile[tx][ty+i]);
}

// ---- fused 3-way transpose for Wq/Wk/Wv: z in [0,36), sel=z/12, head=z%12 ---
__global__ void transpose3_h_kernel(const float* __restrict__ Wq,
                                    const float* __restrict__ Wk,
                                    const float* __restrict__ Wv,
                                    __half* __restrict__ dst)
{
    __shared__ float tile[32][33];
    int z = blockIdx.z;
    int sel = z / Hh, zh = z % Hh;
    const float* src = (sel==0 ? Wq : (sel==1 ? Wk : Wv)) + (size_t)zh*Dm*Em;
    __half* d = dst + ((size_t)sel*Hh + zh)*(size_t)Em*Dm;
    int c0 = blockIdx.x*32, r0 = blockIdx.y*32;
    int tx = threadIdx.x, ty = threadIdx.y;     // 32 x 8
    #pragma unroll
    for (int i=0;i<32;i+=8)
        tile[ty+i][tx] = src[(size_t)(r0+ty+i)*Em + c0+tx];
    __syncthreads();
    #pragma unroll
    for (int i=0;i<32;i+=8)
        d[(size_t)(c0+ty+i)*Dm + r0+tx] = __float2half(tile[tx][ty+i]);
}

// ---------------- pack 3 bias arrays -----------------------------------------
__global__ void pack_bias_kernel(const float* __restrict__ bq,
                                 const float* __restrict__ bk,
                                 const float* __restrict__ bv,
                                 float* __restrict__ dst)
{
    int i = blockIdx.x*256 + threadIdx.x;
    if (i < Hh*Em){
        dst[i]            = bq[i];
        dst[Hh*Em + i]    = bk[i];
        dst[2*Hh*Em + i]  = bv[i];
    }
}

// ---------------- embedding + LayerNorm (half out) --------------------------
__global__ void embed_ln_kernel(const int* __restrict__ ids,
                                const float* __restrict__ tok,
                                const float* __restrict__ seg,
                                const float* __restrict__ gamma,
                                const float* __restrict__ beta,
                                __half* __restrict__ out)
{
    int t = blockIdx.x;
    int s = t % Ss;
    int id = ids[t];
    int sg = (s >= Ss/2 + 1) ? 1 : 0;
    int tid = threadIdx.x;
    float v[3];
    float lsum = 0.f, lsq = 0.f;
    #pragma unroll
    for (int r=0; r<3; r++){
        int i = tid + r*256;
        double di  = (2.0 * (double)i) / 768.0;
        double ang = (double)s * exp(-di * 9.210340371976184);
        float pos  = (i & 1) ? (float)cos(ang) : (float)sin(ang);
        float x = tok[(size_t)id*Dm + i] + seg[(size_t)sg*Dm + i] + pos;
        v[r] = x; lsum += x; lsq += x*x;
    }
    float sum = blockSum(lsum);
    float sq  = blockSum(lsq);
    float mean = sum * (1.f/Dm);
    float var  = sq * (1.f/Dm) - mean*mean;
    float inv  = rsqrtf(var + 1e-5f);
    #pragma unroll
    for (int r=0; r<3; r++){
        int i = tid + r*256;
        out[(size_t)t*Dm + i] = __float2half((v[r]-mean)*inv*gamma[i] + beta[i]);
    }
}

// ---------------- LayerNorm: fp32 in -> half out -----------------------------
__global__ void ln_kernel(const float* __restrict__ in,
                          const float* __restrict__ gamma,
                          const float* __restrict__ beta,
                          __half* __restrict__ out)
{
    int t = blockIdx.x;
    int tid = threadIdx.x;
    float v[3]; float lsum=0.f, lsq=0.f;
    #pragma unroll
    for (int r=0;r<3;r++){
        int i = tid + r*256;
        float x = in[(size_t)t*Dm + i];
        v[r]=x; lsum+=x; lsq+=x*x;
    }
    float sum = blockSum(lsum);
    float sq  = blockSum(lsq);
    float mean = sum * (1.f/Dm);
    float var  = sq * (1.f/Dm) - mean*mean;
    float inv  = rsqrtf(var + 1e-5f);
    #pragma unroll
    for (int r=0;r<3;r++){
        int i = tid + r*256;
        out[(size_t)t*Dm + i] = __float2half((v[r]-mean)*inv*gamma[i] + beta[i]);
    }
}

// ================= FP16 tensor-core GEMM, TB-only, cp.async pipeline =========
// C = act(alpha * A * B^T + bias). A [M][K] half, B [N][K] half.
// BMTx128x32 block tile (BMT=128: 128thr/4 warps/4 stages;
//                        BMT=256: 256thr/8 warps/3 stages), warp tile 64x64.
#define BN 128
#define BKH 32                         // halves per k-tile
#define LROWH 40                       // halves per smem row (80B) -> conflict-free

__device__ __forceinline__ void ldsm4(uint32_t& r0, uint32_t& r1, uint32_t& r2, uint32_t& r3, uint32_t addr){
    asm volatile("ldmatrix.sync.aligned.m8n8.x4.shared.b16 {%0,%1,%2,%3}, [%4];"
        : "=r"(r0),"=r"(r1),"=r"(r2),"=r"(r3) : "r"(addr));
}
__device__ __forceinline__ void mma_f16(float& c0,float& c1,float& c2,float& c3,
                                        uint32_t a0,uint32_t a1,uint32_t a2,uint32_t a3,
                                        uint32_t b0,uint32_t b1){
    asm volatile("mma.sync.aligned.m16n8k16.row.col.f32.f16.f16.f32 "
        "{%0,%1,%2,%3},{%4,%5,%6,%7},{%8,%9},{%0,%1,%2,%3};"
        : "+f"(c0),"+f"(c1),"+f"(c2),"+f"(c3)
        : "r"(a0),"r"(a1),"r"(a2),"r"(a3),"r"(b0),"r"(b1));
}
__device__ __forceinline__ void cp16(uint32_t dst, const __half* src){
    asm volatile("cp.async.cg.shared.global [%0], [%1], 16;" :: "r"(dst), "l"(src));
}

template<int BMT, int ACT, int OUTHALF>
__global__ __launch_bounds__(BMT)
void hgemm_kernel(const __half* __restrict__ Ag, const __half* __restrict__ Bg,
                  const float* __restrict__ biasg, void* __restrict__ Cg,
                  int K, int lda, int ldb, int ldc,
                  int zdiv,
                  size_t sAo, size_t sAi, size_t sBo, size_t sBi,
                  size_t sCo, size_t sCi, size_t sbo, size_t sbi,
                  float alpha)
{
    constexpr int TPB = BMT;                     // threads
    constexpr int NST = (BMT==256) ? 3 : 4;      // pipeline stages
    constexpr int TAB = BMT*80;                  // A tile bytes
    constexpr int STB = (BMT+BN)*80;             // stage bytes

    extern __shared__ char dsm[];
    uint32_t s_base = (uint32_t)__cvta_generic_to_shared(dsm);

    int z  = blockIdx.z;
    int zo = z / zdiv, zi = z % zdiv;
    const __half* A = Ag + (size_t)zo*sAo + (size_t)zi*sAi;
    const __half* B = Bg + (size_t)zo*sBo + (size_t)zi*sBi;
    const float* bias = biasg ? (biasg + (size_t)zo*sbo + (size_t)zi*sbi) : nullptr;

    int m0 = blockIdx.x * BMT;
    int n0 = blockIdx.y * BN;
    int tid = threadIdx.x, lane = tid & 31, warp = tid >> 5;
    int wm, wn;
    if (BMT==256){ wm = warp & 3; wn = warp >> 2; }
    else         { wm = warp & 1; wn = warp >> 1; }

    float acc[4][8][4];
    #pragma unroll
    for (int i=0;i<4;i++)
        #pragma unroll
        for (int j=0;j<8;j++)
            #pragma unroll
            for (int r=0;r<4;r++) acc[i][j][r]=0.f;

    // ldsm byte offsets relative to stage base
    int l15 = lane & 15, lhi = lane >> 4;
    uint32_t a_rel[4];
    #pragma unroll
    for (int i=0;i<4;i++)
        a_rel[i] = (uint32_t)(((wm*64 + i*16 + l15)*LROWH + 8*lhi)*2);
    int brow = (lane & 7) + ((lane & 16) ? 8 : 0);
    int bcol = (lane & 8) ? 8 : 0;   // halves
    uint32_t b_rel[4];
    #pragma unroll
    for (int jj=0;jj<4;jj++)
        b_rel[jj] = (uint32_t)(((wn*64 + jj*16 + brow)*LROWH + bcol)*2 + TAB);

    int nk = K / BKH;
    auto load_stage = [&](int st, int kt){
        uint32_t sb = s_base + (uint32_t)st*STB;
        int k0 = kt*BKH;
        #pragma unroll
        for (int it=0;it<4;it++){                 // A: BMT*4 chunks / TPB = 4
            int c = tid + TPB*it;
            int row = c >> 2, ch = c & 3;
            cp16(sb + (uint32_t)(row*80 + ch*16),
                 A + (size_t)(m0+row)*lda + k0 + ch*8);
        }
        #pragma unroll
        for (int it=0; it<512/TPB; it++){         // B: 128*4 = 512 chunks
            int c = tid + TPB*it;
            int row = c >> 2, ch = c & 3;
            cp16(sb + (uint32_t)(TAB + row*80 + ch*16),
                 B + (size_t)(n0+row)*ldb + k0 + ch*8);
        }
        asm volatile("cp.async.commit_group;");
    };

    #pragma unroll
    for (int p=0; p<NST-1; p++) load_stage(p, p);

    uint32_t a[2][4][4], bf[2][8][2];
    int st = 0;
    for (int i=0; i<nk; i++){
        if (NST==3) asm volatile("cp.async.wait_group 1;");
        else        asm volatile("cp.async.wait_group 2;");
        __syncthreads();
        if (i+NST-1 < nk) load_stage((st+NST-1)%NST, i+NST-1);
        else asm volatile("cp.async.commit_group;");

        uint32_t abase = s_base + (uint32_t)st*STB;
        // prefetch fragments for kk=0
        #pragma unroll
        for (int ii=0;ii<4;ii++)
            ldsm4(a[0][ii][0],a[0][ii][1],a[0][ii][2],a[0][ii][3], abase + a_rel[ii]);
        #pragma unroll
        for (int jj=0;jj<4;jj++)
            ldsm4(bf[0][2*jj][0],bf[0][2*jj][1],bf[0][2*jj+1][0],bf[0][2*jj+1][1], abase + b_rel[jj]);

        #pragma unroll
        for (int kk=0; kk<2; kk++){          // two k16 halves of the 32-k tile
            int cur = kk & 1, nxt = cur^1;
            if (kk == 0){
                #pragma unroll
                for (int ii=0;ii<4;ii++)
                    ldsm4(a[nxt][ii][0],a[nxt][ii][1],a[nxt][ii][2],a[nxt][ii][3],
                          abase + a_rel[ii] + 32);
                #pragma unroll
                for (int jj=0;jj<4;jj++)
                    ldsm4(bf[nxt][2*jj][0],bf[nxt][2*jj][1],bf[nxt][2*jj+1][0],bf[nxt][2*jj+1][1],
                          abase + b_rel[jj] + 32);
            }
            #pragma unroll
            for (int ii=0;ii<4;ii++)
                #pragma unroll
                for (int jj=0;jj<8;jj++)
                    mma_f16(acc[ii][jj][0],acc[ii][jj][1],acc[ii][jj][2],acc[ii][jj][3],
                            a[cur][ii][0],a[cur][ii][1],a[cur][ii][2],a[cur][ii][3],
                            bf[cur][jj][0],bf[cur][jj][1]);
        }
        st = (st+1==NST) ? 0 : st+1;
    }

    // epilogue
    int g = lane >> 2, tg = lane & 3;
    #pragma unroll
    for (int i=0;i<4;i++){
        #pragma unroll
        for (int j=0;j<8;j++){
            int ncol = n0 + wn*64 + j*8 + 2*tg;
            float b0v = bias ? __ldg(&bias[ncol])   : 0.f;
            float b1v = bias ? __ldg(&bias[ncol+1]) : 0.f;
            #pragma unroll
            for (int h=0;h<2;h++){
                int mrow = m0 + wm*64 + i*16 + g + h*8;
                float v0 = acc[i][j][2*h+0]*alpha + b0v;
                float v1 = acc[i][j][2*h+1]*alpha + b1v;
                if (ACT==1){
                    v0 = 0.5f*v0*(1.0f + erff(v0*0.7071067811865475f));
                    v1 = 0.5f*v1*(1.0f + erff(v1*0.7071067811865475f));
                }
                size_t coff = (size_t)zo*sCo + (size_t)zi*sCi + (size_t)mrow*ldc + ncol;
                if (OUTHALF){
                    __half2* cp = (__half2*)((__half*)Cg + coff);
                    *cp = __floats2half2_rn(v0, v1);
                } else {
                    float2 o; o.x=v0; o.y=v1;
                    *(float2*)((float*)Cg + coff) = o;
                }
            }
        }
    }
}

// ---------------- attention softmax (half in/out) ---------------
__global__ void attn_softmax_kernel(__half* __restrict__ sc,
                                    const unsigned char* __restrict__ mask)
{
    int r = blockIdx.x;
    int z = r / Ss;
    int s = r % Ss;
    int b = z / Hh;
    __half* row = sc + (size_t)r * Ss;
    const unsigned char* mrow = mask + ((size_t)b*Ss + s)*Ss;
    int tid = threadIdx.x;
    float v[4]; float mx = -F_INF;
    #pragma unroll
    for (int rr=0;rr<4;rr++){
        int t = tid + rr*128;
        float x = __half2float(row[t]);
        if (mrow[t]) x = -1e9f;
        v[rr] = x; mx = fmaxf(mx, x);
    }
    mx = blockMax(mx);
    float ls = 0.f;
    #pragma unroll
    for (int rr=0;rr<4;rr++){ v[rr] = __expf(v[rr]-mx); ls += v[rr]; }
    float sum = blockSum(ls);
    float inv = 1.f/sum;
    #pragma unroll
    for (int rr=0;rr<4;rr++){
        int t = tid + rr*128;
        row[t] = __float2half(v[rr]*inv);
    }
}

// ---------------- log-softmax over vocab: half logits -> fp32 out ------------
__global__ __launch_bounds__(512) void logsoftmax_h_kernel(const __half* __restrict__ logits,
                                                           float* __restrict__ out)
{
    const int NV2 = Vv/2;   // 16000 half2 per row
    int t = blockIdx.x;
    const __half2* row = (const __half2*)(logits + (size_t)t * Vv);
    float2* orow = (float2*)(out + (size_t)t * Vv);
    int tid = threadIdx.x;
    __half2 v[32];
    float mx = -F_INF;
    #pragma unroll
    for (int k=0;k<32;k++){
        int i = tid + k*512;
        if (i < NV2){
            v[k] = row[i];
            float2 f = __half22float2(v[k]);
            mx = fmaxf(mx, fmaxf(f.x, f.y));
        }
    }
    mx = blockMax(mx);
    float ls = 0.f;
    #pragma unroll
    for (int k=0;k<32;k++){
        int i = tid + k*512;
        if (i < NV2){
            float2 f = __half22float2(v[k]);
            ls += __expf(f.x-mx) + __expf(f.y-mx);
        }
    }
    float sum = blockSum(ls);
    float sub = mx + logf(sum);
    #pragma unroll
    for (int k=0;k<32;k++){
        int i = tid + k*512;
        if (i < NV2){
            float2 f = __half22float2(v[k]);
            float2 o; o.x = f.x - sub; o.y = f.y - sub;
            orow[i] = o;
        }
    }
}

// ---------------- cls head (half enc) ----------------------------
__global__ void cls_kernel(const __half* __restrict__ enc,
                           const float* __restrict__ Wc,
                           const float* __restrict__ bc,
                           float* __restrict__ out)
{
    int b = blockIdx.x >> 1, c = blockIdx.x & 1;
    const __half* row = enc + (size_t)b*Ss*Dm;
    float lsum = 0.f;
    for (int i=threadIdx.x; i<Dm; i+=128)
        lsum += __half2float(row[i]) * Wc[(size_t)i*2 + c];
    float sum = blockSum(lsum);
    if (threadIdx.x==0)
        out[(size_t)Tt*Vv + b*2 + c] = sum + bc[c];
}

// ---------------- host launcher ---------------------------------------------
template<int BMT, int ACT, int OUTHALF>
static inline void gemm_h(const __half* A, const __half* B, const float* bias, void* C,
                          int M,int N,int K,int lda,int ldb,int ldc,
                          int gz, int zdiv,
                          size_t sAo,size_t sAi,size_t sBo,size_t sBi,
                          size_t sCo,size_t sCi,size_t sbo,size_t sbi,
                          float alpha)
{
    constexpr int NST = (BMT==256) ? 3 : 4;
    constexpr int SMEM = NST*(BMT+BN)*80;
    cudaFuncSetAttribute(hgemm_kernel<BMT,ACT,OUTHALF>,
                         cudaFuncAttributeMaxDynamicSharedMemorySize, SMEM);
    dim3 grid(M/BMT, N/BN, gz), blk(BMT);
    hgemm_kernel<BMT,ACT,OUTHALF><<<grid,blk,SMEM>>>(A,B,bias,C,K,lda,ldb,ldc,zdiv,
        sAo,sAi,sBo,sBi,sCo,sCi,sbo,sbi,alpha);
}

extern "C" void kernel_launch(void* const* d_in, const int* in_sizes, int n_in,
                              void* d_out, int out_size)
{
    (void)in_sizes; (void)n_in; (void)out_size;
    const int*   ids   = (const int*)  d_in[0];
    const unsigned char* mask = (const unsigned char*)d_in[1];
    const float* tok   = (const float*)d_in[2];
    const float* seg   = (const float*)d_in[3];
    const float* lng_e = (const float*)d_in[4];
    const float* lnb_e = (const float*)d_in[5];
    const float* Wq    = (const float*)d_in[6];
    const float* bq    = (const float*)d_in[7];
    const float* Wk    = (const float*)d_in[8];
    const float* bk    = (const float*)d_in[9];
    const float* Wv    = (const float*)d_in[10];
    const float* bv    = (const float*)d_in[11];
    const float* Wo    = (const float*)d_in[12];
    const float* bo    = (const float*)d_in[13];
    const float* lng_a = (const float*)d_in[14];
    const float* lnb_a = (const float*)d_in[15];
    const float* W1    = (const float*)d_in[16];
    const float* b1    = (const float*)d_in[17];
    const float* W2    = (const float*)d_in[18];
    const float* b2    = (const float*)d_in[19];
    const float* lng_f = (const float*)d_in[20];
    const float* lnb_f = (const float*)d_in[21];
    const float* Wp    = (const float*)d_in[22];
    const float* bp    = (const float*)d_in[23];
    const float* Wc    = (const float*)d_in[24];
    const float* bc    = (const float*)d_in[25];
    float* out = (float*)d_out;

    __half *gx,*gqkv,*gvT,*gsc,*gctx,*gh1,*gh2,*genc,*glog;
    __half *wqkvt,*wot,*w1t,*w2t,*wpt;
    float *gf1,*bqkv;
    cudaGetSymbolAddress((void**)&gx,   g_x);
    cudaGetSymbolAddress((void**)&gqkv, g_qkv);
    cudaGetSymbolAddress((void**)&gvT,  g_vT);
    cudaGetSymbolAddress((void**)&gsc,  g_sc);
    cudaGetSymbolAddress((void**)&gctx, g_ctx);
    cudaGetSymbolAddress((void**)&gh1,  g_h1);
    cudaGetSymbolAddress((void**)&gh2,  g_h2);
    cudaGetSymbolAddress((void**)&genc, g_enc);
    cudaGetSymbolAddress((void**)&gf1,  g_f1);
    cudaGetSymbolAddress((void**)&glog, g_logits);
    cudaGetSymbolAddress((void**)&wqkvt,g_wqkvt);
    cudaGetSymbolAddress((void**)&bqkv, g_bqkv);
    cudaGetSymbolAddress((void**)&wot,  g_wot);
    cudaGetSymbolAddress((void**)&w1t,  g_w1t);
    cudaGetSymbolAddress((void**)&w2t,  g_w2t);
    cudaGetSymbolAddress((void**)&wpt,  g_wpt);

    __half* gq = gqkv;
    __half* gk = gqkv + (size_t)Hh*Tt*Em;
    __half* gv = gqkv + 2*(size_t)Hh*Tt*Em;

    dim3 tb(32,8);
    // launch 0: fused QKV weight transpose; 1: bias pack; 2: embedding
    transpose3_h_kernel<<<dim3(Em/32, Dm/32, 3*Hh), tb>>>(Wq, Wk, Wv, wqkvt);     // 0
    pack_bias_kernel<<<(Hh*Em+255)/256,256>>>(bq, bk, bv, bqkv);                  // 1
    embed_ln_kernel<<<Tt,256>>>(ids, tok, seg, lng_e, lnb_e, gx);                 // 2

    // launch 3: fused QKV GEMM (BM=256 tile)
    size_t sW = (size_t)Em*Dm, sC = (size_t)Tt*Em;
    gemm_h<256,0,1>(gx,wqkvt,bqkv,gqkv, Tt,Em,Dm, Dm,Dm,Em, 3*Hh,1,
                0,0, sW,0, sC,0, Em,0, 1.f);

    // deferred weight transposes (needed later)
    transpose_h_kernel<float><<<dim3(Dm/32, (Hh*Em)/32, 1), tb>>>(Wo, wot, Hh*Em, Dm);
    transpose_h_kernel<float><<<dim3(Em/32, Dm/32, 1), tb>>>(W1, w1t, Dm, Em);
    transpose_h_kernel<float><<<dim3(Dm/32, Em/32, 1), tb>>>(W2, w2t, Em, Dm);
    transpose_h_kernel<float><<<dim3(Vv/32, Dm/32, 1), tb>>>(Wp, wpt, Dm, Vv);

    // transpose V per head: [H][T][E] -> [H][E][T]
    transpose_h_kernel<__half><<<dim3(Em/32, Tt/32, Hh), tb>>>(gv, gvT, Tt, Em);

    // 3) scores = Q K^T / sqrt(S): z = b*H + h
    size_t qO = (size_t)Ss*Em, qI = (size_t)Tt*Em;
    gemm_h<128,0,1>(gq,gk,nullptr,gsc, Ss,Ss,Em, Em,Em,Ss, Bb*Hh,Hh,
            qO,qI, qO,qI, (size_t)Hh*Ss*Ss,(size_t)Ss*Ss, 0,0,
            0.04419417382415922f);

    // 4) softmax (+mask)
    attn_softmax_kernel<<<Bb*Hh*Ss,128>>>(gsc, mask);

    // 5) ctx = attn @ V: B = Vt [H][E][T]
    gemm_h<128,0,1>(gsc,gvT,nullptr,gctx, Ss,Em,Ss, Ss,Tt,Hh*Em, Bb*Hh,Hh,
            (size_t)Hh*Ss*Ss,(size_t)Ss*Ss, (size_t)Ss,(size_t)Em*Tt,
            (size_t)Ss*Hh*Em,(size_t)Em, 0,0, 1.f);

    // 6) attn output proj (fp32 out) + LN (half out)
    gemm_h<128,0,0>(gctx,wot,bo,gf1, Tt,Dm,Hh*Em, Hh*Em,Hh*Em,Dm, 1,1,
            0,0, 0,0, 0,0, 0,0, 1.f);
    ln_kernel<<<Tt,256>>>(gf1, lng_a, lnb_a, gh2);

    // 7) FFN: gelu half out, then W2 fp32 out, LN half out
    gemm_h<128,1,1>(gh2,w1t,b1,gh1, Tt,Em,Dm, Dm,Dm,Em, 1,1, 0,0,0,0,0,0,0,0, 1.f);
    gemm_h<128,0,0>(gh1,w2t,b2,gf1, Tt,Dm,Em, Em,Em,Dm, 1,1, 0,0,0,0,0,0,0,0, 1.f);
    ln_kernel<<<Tt,256>>>(gf1, lng_f, lnb_f, genc);

    // 8) vocab logits (fp16 staging, BM=256 tile) -> log-softmax -> fp32 out
    gemm_h<256,0,1>(genc,wpt,bp,glog, Tt,Vv,Dm, Dm,Dm,Vv, 1,1, 0,0,0,0,0,0,0,0, 1.f);
    logsoftmax_h_kernel<<<Tt,512>>>(glog, out);

    // 9) cls head
    cls_kernel<<<8,128>>>(genc, Wc, bc, out);
}

// round 14
// speedup vs baseline: 1.0710x; 1.0710x over previous
#include <cuda_runtime.h>
#include <cuda_fp16.h>
#include <math.h>
#include <stdint.h>

#define F_INF __int_as_float(0x7f800000)

// Problem dims
#define Dm 768
#define Em 768
#define Hh 12
#define Bb 4
#define Ss 512
#define Vv 32000
#define Tt (Bb*Ss)   // 2048

// ---------------- scratch (device globals) ----------------------------------
__device__ __half g_x[Tt*Dm];              // embed+LN out
__device__ __half g_qkv[3*Hh*Tt*Em];       // [3][H][T][E]  (q,k,v slabs)
__device__ __half g_vT[Hh*Em*Tt];          // V transposed per head: [H][E][T]
__device__ __half g_sc[Bb*Hh*Ss*Ss];       // scores / attn
__device__ __half g_ctx[Tt*Hh*Em];
__device__ __half g_h1[Tt*Em];             // gelu intermediate
__device__ __half g_h2[Tt*Dm];             // LN(attn) out
__device__ __half g_enc[Tt*Dm];            // final LN out
__device__ float  g_f1[Tt*Dm];             // fp32 staging for LN inputs
__device__ __half g_logits[(size_t)Tt*Vv]; // fp16 logits staging
// packed transposed half weights
__device__ __half g_wqkvt[3*Hh*Em*Dm];     // [3][H][E][D]
__device__ float  g_bqkv[3*Hh*Em];         // packed fp32 biases
__device__ __half g_wot[Dm*Hh*Em];
__device__ __half g_w1t[Em*Dm];
__device__ __half g_w2t[Dm*Em];
__device__ __half g_wpt[Vv*Dm];

// ---------------- helpers ----------------
__device__ __forceinline__ float warpSum(float v){
    #pragma unroll
    for (int o=16;o;o>>=1) v += __shfl_xor_sync(0xffffffffu, v, o);
    return v;
}
__device__ __forceinline__ float warpMax(float v){
    #pragma unroll
    for (int o=16;o;o>>=1) v = fmaxf(v, __shfl_xor_sync(0xffffffffu, v, o));
    return v;
}
__device__ float blockSum(float v){
    __shared__ float sh[33];
    int lane = threadIdx.x & 31, wid = threadIdx.x >> 5;
    v = warpSum(v);
    __syncthreads();
    if (lane==0) sh[wid] = v;
    __syncthreads();
    if (wid==0){
        int nw = blockDim.x >> 5;
        float t = (lane < nw) ? sh[lane] : 0.f;
        t = warpSum(t);
        if (lane==0) sh[32] = t;
    }
    __syncthreads();
    return sh[32];
}
__device__ float blockMax(float v){
    __shared__ float sh[33];
    int lane = threadIdx.x & 31, wid = threadIdx.x >> 5;
    v = warpMax(v);
    __syncthreads();
    if (lane==0) sh[wid] = v;
    __syncthreads();
    if (wid==0){
        int nw = blockDim.x >> 5;
        float t = (lane < nw) ? sh[lane] : -F_INF;
        t = warpMax(t);
        if (lane==0) sh[32] = t;
    }
    __syncthreads();
    return sh[32];
}

// ---------------- transpose: src[R][C] -> dst[C][R] (to half) ---------------
template<typename TI>
__global__ void transpose_h_kernel(const TI* __restrict__ src,
                                   __half* __restrict__ dst,
                                   int R, int C)
{
    __shared__ float tile[32][33];
    int z = blockIdx.z;
    src += (size_t)z*R*C;
    dst += (size_t)z*R*C;
    int c0 = blockIdx.x*32, r0 = blockIdx.y*32;
    int tx = threadIdx.x, ty = threadIdx.y;     // 32 x 8
    #pragma unroll
    for (int i=0;i<32;i+=8)
        tile[ty+i][tx] = (float)src[(size_t)(r0+ty+i)*C + c0+tx];
    __syncthreads();
    #pragma unroll
    for (int i=0;i<32;i+=8)
        dst[(size_t)(c0+ty+i)*R + r0+tx] = __float2half(tile[tx][ty+i]);
}

// ---- fused 3-way transpose for Wq/Wk/Wv: z in [0,36), sel=z/12, head=z%12 ---
__global__ void transpose3_h_kernel(const float* __restrict__ Wq,
                                    const float* __restrict__ Wk,
                                    const float* __restrict__ Wv,
                                    __half* __restrict__ dst)
{
    __shared__ float tile[32][33];
    int z = blockIdx.z;
    int sel = z / Hh, zh = z % Hh;
    const float* src = (sel==0 ? Wq : (sel==1 ? Wk : Wv)) + (size_t)zh*Dm*Em;
    __half* d = dst + ((size_t)sel*Hh + zh)*(size_t)Em*Dm;
    int c0 = blockIdx.x*32, r0 = blockIdx.y*32;
    int tx = threadIdx.x, ty = threadIdx.y;     // 32 x 8
    #pragma unroll
    for (int i=0;i<32;i+=8)
        tile[ty+i][tx] = src[(size_t)(r0+ty+i)*Em + c0+tx];
    __syncthreads();
    #pragma unroll
    for (int i=0;i<32;i+=8)
        d[(size_t)(c0+ty+i)*Dm + r0+tx] = __float2half(tile[tx][ty+i]);
}

// ---------------- pack 3 bias arrays -----------------------------------------
__global__ void pack_bias_kernel(const float* __restrict__ bq,
                                 const float* __restrict__ bk,
                                 const float* __restrict__ bv,
                                 float* __restrict__ dst)
{
    int i = blockIdx.x*256 + threadIdx.x;
    if (i < Hh*Em){
        dst[i]            = bq[i];
        dst[Hh*Em + i]    = bk[i];
        dst[2*Hh*Em + i]  = bv[i];
    }
}

// ---------------- embedding + LayerNorm (half out) --------------------------
__global__ void embed_ln_kernel(const int* __restrict__ ids,
                                const float* __restrict__ tok,
                                const float* __restrict__ seg,
                                const float* __restrict__ gamma,
                                const float* __restrict__ beta,
                                __half* __restrict__ out)
{
    int t = blockIdx.x;
    int s = t % Ss;
    int id = ids[t];
    int sg = (s >= Ss/2 + 1) ? 1 : 0;
    int tid = threadIdx.x;
    float v[3];
    float lsum = 0.f, lsq = 0.f;
    #pragma unroll
    for (int r=0; r<3; r++){
        int i = tid + r*256;
        double di  = (2.0 * (double)i) / 768.0;
        double ang = (double)s * exp(-di * 9.210340371976184);
        float pos  = (i & 1) ? (float)cos(ang) : (float)sin(ang);
        float x = tok[(size_t)id*Dm + i] + seg[(size_t)sg*Dm + i] + pos;
        v[r] = x; lsum += x; lsq += x*x;
    }
    float sum = blockSum(lsum);
    float sq  = blockSum(lsq);
    float mean = sum * (1.f/Dm);
    float var  = sq * (1.f/Dm) - mean*mean;
    float inv  = rsqrtf(var + 1e-5f);
    #pragma unroll
    for (int r=0; r<3; r++){
        int i = tid + r*256;
        out[(size_t)t*Dm + i] = __float2half((v[r]-mean)*inv*gamma[i] + beta[i]);
    }
}

// ---------------- LayerNorm: fp32 in -> half out -----------------------------
__global__ void ln_kernel(const float* __restrict__ in,
                          const float* __restrict__ gamma,
                          const float* __restrict__ beta,
                          __half* __restrict__ out)
{
    int t = blockIdx.x;
    int tid = threadIdx.x;
    float v[3]; float lsum=0.f, lsq=0.f;
    #pragma unroll
    for (int r=0;r<3;r++){
        int i = tid + r*256;
        float x = in[(size_t)t*Dm + i];
        v[r]=x; lsum+=x; lsq+=x*x;
    }
    float sum = blockSum(lsum);
    float sq  = blockSum(lsq);
    float mean = sum * (1.f/Dm);
    float var  = sq * (1.f/Dm) - mean*mean;
    float inv  = rsqrtf(var + 1e-5f);
    #pragma unroll
    for (int r=0;r<3;r++){
        int i = tid + r*256;
        out[(size_t)t*Dm + i] = __float2half((v[r]-mean)*inv*gamma[i] + beta[i]);
    }
}

// ================= FP16 tensor-core GEMM, TB-only, cp.async 3-stage ==========
// C = act(alpha * A * B^T + bias). A [M][K] half, B [N][K] half.
// 128x128x32 block tile, 128 threads (4 warps 2x2), warp tile 64x64,
// m16n8k16 fp16 mma with fp32 accumulate. min 3 CTAs/SM (register-capped).
#define BM 128
#define BN 128
#define BKH 32                         // halves per k-tile
#define LROWH 40                       // halves per smem row (80B) -> conflict-free
#define TILE_BYTES (BM*LROWH*2)        // 10240
#define STAGE_BYTES (2*TILE_BYTES)     // 20480
#define NSTAGE 3
#define SMEM_BYTES  (NSTAGE*STAGE_BYTES)  // 61440

__device__ __forceinline__ void ldsm4(uint32_t& r0, uint32_t& r1, uint32_t& r2, uint32_t& r3, uint32_t addr){
    asm volatile("ldmatrix.sync.aligned.m8n8.x4.shared.b16 {%0,%1,%2,%3}, [%4];"
        : "=r"(r0),"=r"(r1),"=r"(r2),"=r"(r3) : "r"(addr));
}
__device__ __forceinline__ void mma_f16(float& c0,float& c1,float& c2,float& c3,
                                        uint32_t a0,uint32_t a1,uint32_t a2,uint32_t a3,
                                        uint32_t b0,uint32_t b1){
    asm volatile("mma.sync.aligned.m16n8k16.row.col.f32.f16.f16.f32 "
        "{%0,%1,%2,%3},{%4,%5,%6,%7},{%8,%9},{%0,%1,%2,%3};"
        : "+f"(c0),"+f"(c1),"+f"(c2),"+f"(c3)
        : "r"(a0),"r"(a1),"r"(a2),"r"(a3),"r"(b0),"r"(b1));
}
__device__ __forceinline__ void cp16(uint32_t dst, const __half* src){
    asm volatile("cp.async.cg.shared.global [%0], [%1], 16;" :: "r"(dst), "l"(src));
}

template<int ACT, int OUTHALF>
__global__ __launch_bounds__(128, 3)
void hgemm_kernel(const __half* __restrict__ Ag, const __half* __restrict__ Bg,
                  const float* __restrict__ biasg, void* __restrict__ Cg,
                  int K, int lda, int ldb, int ldc,
                  int zdiv,
                  size_t sAo, size_t sAi, size_t sBo, size_t sBi,
                  size_t sCo, size_t sCi, size_t sbo, size_t sbi,
                  float alpha)
{
    extern __shared__ char dsm[];
    uint32_t s_base = (uint32_t)__cvta_generic_to_shared(dsm);

    int z  = blockIdx.z;
    int zo = z / zdiv, zi = z % zdiv;
    const __half* A = Ag + (size_t)zo*sAo + (size_t)zi*sAi;
    const __half* B = Bg + (size_t)zo*sBo + (size_t)zi*sBi;
    const float* bias = biasg ? (biasg + (size_t)zo*sbo + (size_t)zi*sbi) : nullptr;

    int m0 = blockIdx.x * BM;
    int n0 = blockIdx.y * BN;
    int tid = threadIdx.x, lane = tid & 31, warp = tid >> 5;
    int wm = warp & 1, wn = warp >> 1;      // warp tile (wm*64, wn*64)

    float acc[4][8][4];
    #pragma unroll
    for (int i=0;i<4;i++)
        #pragma unroll
        for (int j=0;j<8;j++)
            #pragma unroll
            for (int r=0;r<4;r++) acc[i][j][r]=0.f;

    // ldsm byte offsets relative to stage base
    int l15 = lane & 15, lhi = lane >> 4;
    uint32_t a_rel[4];
    #pragma unroll
    for (int i=0;i<4;i++)
        a_rel[i] = (uint32_t)(((wm*64 + i*16 + l15)*LROWH + 8*lhi)*2);
    int brow = (lane & 7) + ((lane & 16) ? 8 : 0);
    int bcol = (lane & 8) ? 8 : 0;   // halves
    uint32_t b_rel[4];
    #pragma unroll
    for (int jj=0;jj<4;jj++)
        b_rel[jj] = (uint32_t)(((wn*64 + jj*16 + brow)*LROWH + bcol)*2 + TILE_BYTES);

    int nk = K / BKH;
    auto load_stage = [&](int st, int kt){
        uint32_t sb = s_base + (uint32_t)st*STAGE_BYTES;
        int k0 = kt*BKH;
        #pragma unroll
        for (int it=0;it<4;it++){
            int c = tid + 128*it;
            int row = c >> 2, ch = c & 3;
            cp16(sb + (uint32_t)(row*80 + ch*16),
                 A + (size_t)(m0+row)*lda + k0 + ch*8);
        }
        #pragma unroll
        for (int it=0;it<4;it++){
            int c = tid + 128*it;
            int row = c >> 2, ch = c & 3;
            cp16(sb + (uint32_t)(TILE_BYTES + row*80 + ch*16),
                 B + (size_t)(n0+row)*ldb + k0 + ch*8);
        }
        asm volatile("cp.async.commit_group;");
    };

    load_stage(0, 0);
    load_stage(1, 1);

    int st = 0;
    for (int i=0; i<nk; i++){
        asm volatile("cp.async.wait_group 1;");
        __syncthreads();
        if (i+2 < nk) load_stage((st+2)%3, i+2);
        else asm volatile("cp.async.commit_group;");

        uint32_t abase = s_base + (uint32_t)st*STAGE_BYTES;
        // single-buffer fragments: two k16 halves per 32-k tile
        #pragma unroll
        for (int kk=0; kk<2; kk++){
            uint32_t a[4][4], bf[8][2];
            #pragma unroll
            for (int ii=0;ii<4;ii++)
                ldsm4(a[ii][0],a[ii][1],a[ii][2],a[ii][3], abase + a_rel[ii] + kk*32);
            #pragma unroll
            for (int jj=0;jj<4;jj++)
                ldsm4(bf[2*jj][0],bf[2*jj][1],bf[2*jj+1][0],bf[2*jj+1][1],
                      abase + b_rel[jj] + kk*32);
            #pragma unroll
            for (int ii=0;ii<4;ii++)
                #pragma unroll
                for (int jj=0;jj<8;jj++)
                    mma_f16(acc[ii][jj][0],acc[ii][jj][1],acc[ii][jj][2],acc[ii][jj][3],
                            a[ii][0],a[ii][1],a[ii][2],a[ii][3],
                            bf[jj][0],bf[jj][1]);
        }
        st = (st+1)%3;
    }

    // epilogue
    int g = lane >> 2, tg = lane & 3;
    #pragma unroll
    for (int i=0;i<4;i++){
        #pragma unroll
        for (int j=0;j<8;j++){
            int ncol = n0 + wn*64 + j*8 + 2*tg;
            float b0v = bias ? __ldg(&bias[ncol])   : 0.f;
            float b1v = bias ? __ldg(&bias[ncol+1]) : 0.f;
            #pragma unroll
            for (int h=0;h<2;h++){
                int mrow = m0 + wm*64 + i*16 + g + h*8;
                float v0 = acc[i][j][2*h+0]*alpha + b0v;
                float v1 = acc[i][j][2*h+1]*alpha + b1v;
                if (ACT==1){
                    v0 = 0.5f*v0*(1.0f + erff(v0*0.7071067811865475f));
                    v1 = 0.5f*v1*(1.0f + erff(v1*0.7071067811865475f));
                }
                size_t coff = (size_t)zo*sCo + (size_t)zi*sCi + (size_t)mrow*ldc + ncol;
                if (OUTHALF){
                    __half2* cp = (__half2*)((__half*)Cg + coff);
                    *cp = __floats2half2_rn(v0, v1);
                } else {
                    float2 o; o.x=v0; o.y=v1;
                    *(float2*)((float*)Cg + coff) = o;
                }
            }
        }
    }
}

// ---------------- attention softmax (half in/out) ---------------
__global__ void attn_softmax_kernel(__half* __restrict__ sc,
                                    const unsigned char* __restrict__ mask)
{
    int r = blockIdx.x;
    int z = r / Ss;
    int s = r % Ss;
    int b = z / Hh;
    __half* row = sc + (size_t)r * Ss;
    const unsigned char* mrow = mask + ((size_t)b*Ss + s)*Ss;
    int tid = threadIdx.x;
    float v[4]; float mx = -F_INF;
    #pragma unroll
    for (int rr=0;rr<4;rr++){
        int t = tid + rr*128;
        float x = __half2float(row[t]);
        if (mrow[t]) x = -1e9f;
        v[rr] = x; mx = fmaxf(mx, x);
    }
    mx = blockMax(mx);
    float ls = 0.f;
    #pragma unroll
    for (int rr=0;rr<4;rr++){ v[rr] = __expf(v[rr]-mx); ls += v[rr]; }
    float sum = blockSum(ls);
    float inv = 1.f/sum;
    #pragma unroll
    for (int rr=0;rr<4;rr++){
        int t = tid + rr*128;
        row[t] = __float2half(v[rr]*inv);
    }
}

// ---------------- log-softmax over vocab: half logits -> fp32 out ------------
__global__ __launch_bounds__(512) void logsoftmax_h_kernel(const __half* __restrict__ logits,
                                                           float* __restrict__ out)
{
    const int NV2 = Vv/2;   // 16000 half2 per row
    int t = blockIdx.x;
    const __half2* row = (const __half2*)(logits + (size_t)t * Vv);
    float2* orow = (float2*)(out + (size_t)t * Vv);
    int tid = threadIdx.x;
    __half2 v[32];
    float mx = -F_INF;
    #pragma unroll
    for (int k=0;k<32;k++){
        int i = tid + k*512;
        if (i < NV2){
            v[k] = row[i];
            float2 f = __half22float2(v[k]);
            mx = fmaxf(mx, fmaxf(f.x, f.y));
        }
    }
    mx = blockMax(mx);
    float ls = 0.f;
    #pragma unroll
    for (int k=0;k<32;k++){
        int i = tid + k*512;
        if (i < NV2){
            float2 f = __half22float2(v[k]);
            ls += __expf(f.x-mx) + __expf(f.y-mx);
        }
    }
    float sum = blockSum(ls);
    float sub = mx + logf(sum);
    #pragma unroll
    for (int k=0;k<32;k++){
        int i = tid + k*512;
        if (i < NV2){
            float2 f = __half22float2(v[k]);
            float2 o; o.x = f.x - sub; o.y = f.y - sub;
            orow[i] = o;
        }
    }
}

// ---------------- cls head (half enc) ----------------------------
__global__ void cls_kernel(const __half* __restrict__ enc,
                           const float* __restrict__ Wc,
                           const float* __restrict__ bc,
                           float* __restrict__ out)
{
    int b = blockIdx.x >> 1, c = blockIdx.x & 1;
    const __half* row = enc + (size_t)b*Ss*Dm;
    float lsum = 0.f;
    for (int i=threadIdx.x; i<Dm; i+=128)
        lsum += __half2float(row[i]) * Wc[(size_t)i*2 + c];
    float sum = blockSum(lsum);
    if (threadIdx.x==0)
        out[(size_t)Tt*Vv + b*2 + c] = sum + bc[c];
}

// ---------------- host launcher ---------------------------------------------
template<int ACT, int OUTHALF>
static inline void gemm_h(const __half* A, const __half* B, const float* bias, void* C,
                          int M,int N,int K,int lda,int ldb,int ldc,
                          int gz, int zdiv,
                          size_t sAo,size_t sAi,size_t sBo,size_t sBi,
                          size_t sCo,size_t sCi,size_t sbo,size_t sbi,
                          float alpha)
{
    cudaFuncSetAttribute(hgemm_kernel<ACT,OUTHALF>,
                         cudaFuncAttributeMaxDynamicSharedMemorySize, SMEM_BYTES);
    dim3 grid(M/BM, N/BN, gz), blk(128);
    hgemm_kernel<ACT,OUTHALF><<<grid,blk,SMEM_BYTES>>>(A,B,bias,C,K,lda,ldb,ldc,zdiv,
        sAo,sAi,sBo,sBi,sCo,sCi,sbo,sbi,alpha);
}

extern "C" void kernel_launch(void* const* d_in, const int* in_sizes, int n_in,
                              void* d_out, int out_size)
{
    (void)in_sizes; (void)n_in; (void)out_size;
    const int*   ids   = (const int*)  d_in[0];
    const unsigned char* mask = (const unsigned char*)d_in[1];
    const float* tok   = (const float*)d_in[2];
    const float* seg   = (const float*)d_in[3];
    const float* lng_e = (const float*)d_in[4];
    const float* lnb_e = (const float*)d_in[5];
    const float* Wq    = (const float*)d_in[6];
    const float* bq    = (const float*)d_in[7];
    const float* Wk    = (const float*)d_in[8];
    const float* bk    = (const float*)d_in[9];
    const float* Wv    = (const float*)d_in[10];
    const float* bv    = (const float*)d_in[11];
    const float* Wo    = (const float*)d_in[12];
    const float* bo    = (const float*)d_in[13];
    const float* lng_a = (const float*)d_in[14];
    const float* lnb_a = (const float*)d_in[15];
    const float* W1    = (const float*)d_in[16];
    const float* b1    = (const float*)d_in[17];
    const float* W2    = (const float*)d_in[18];
    const float* b2    = (const float*)d_in[19];
    const float* lng_f = (const float*)d_in[20];
    const float* lnb_f = (const float*)d_in[21];
    const float* Wp    = (const float*)d_in[22];
    const float* bp    = (const float*)d_in[23];
    const float* Wc    = (const float*)d_in[24];
    const float* bc    = (const float*)d_in[25];
    float* out = (float*)d_out;

    __half *gx,*gqkv,*gvT,*gsc,*gctx,*gh1,*gh2,*genc,*glog;
    __half *wqkvt,*wot,*w1t,*w2t,*wpt;
    float *gf1,*bqkv;
    cudaGetSymbolAddress((void**)&gx,   g_x);
    cudaGetSymbolAddress((void**)&gqkv, g_qkv);
    cudaGetSymbolAddress((void**)&gvT,  g_vT);
    cudaGetSymbolAddress((void**)&gsc,  g_sc);
    cudaGetSymbolAddress((void**)&gctx, g_ctx);
    cudaGetSymbolAddress((void**)&gh1,  g_h1);
    cudaGetSymbolAddress((void**)&gh2,  g_h2);
    cudaGetSymbolAddress((void**)&genc, g_enc);
    cudaGetSymbolAddress((void**)&gf1,  g_f1);
    cudaGetSymbolAddress((void**)&glog, g_logits);
    cudaGetSymbolAddress((void**)&wqkvt,g_wqkvt);
    cudaGetSymbolAddress((void**)&bqkv, g_bqkv);
    cudaGetSymbolAddress((void**)&wot,  g_wot);
    cudaGetSymbolAddress((void**)&w1t,  g_w1t);
    cudaGetSymbolAddress((void**)&w2t,  g_w2t);
    cudaGetSymbolAddress((void**)&wpt,  g_wpt);

    __half* gq = gqkv;
    __half* gk = gqkv + (size_t)Hh*Tt*Em;
    __half* gv = gqkv + 2*(size_t)Hh*Tt*Em;

    dim3 tb(32,8);
    // launch 0: fused QKV weight transpose; 1: bias pack; 2: embedding
    transpose3_h_kernel<<<dim3(Em/32, Dm/32, 3*Hh), tb>>>(Wq, Wk, Wv, wqkvt);     // 0
    pack_bias_kernel<<<(Hh*Em+255)/256,256>>>(bq, bk, bv, bqkv);                  // 1
    embed_ln_kernel<<<Tt,256>>>(ids, tok, seg, lng_e, lnb_e, gx);                 // 2

    // launch 3: fused QKV GEMM (captured by ncu at -s 5 with +2 offset)
    size_t sW = (size_t)Em*Dm, sC = (size_t)Tt*Em;
    gemm_h<0,1>(gx,wqkvt,bqkv,gqkv, Tt,Em,Dm, Dm,Dm,Em, 3*Hh,1,
                0,0, sW,0, sC,0, Em,0, 1.f);

    // deferred weight transposes (needed later)
    transpose_h_kernel<float><<<dim3(Dm/32, (Hh*Em)/32, 1), tb>>>(Wo, wot, Hh*Em, Dm);
    transpose_h_kernel<float><<<dim3(Em/32, Dm/32, 1), tb>>>(W1, w1t, Dm, Em);
    transpose_h_kernel<float><<<dim3(Dm/32, Em/32, 1), tb>>>(W2, w2t, Em, Dm);
    transpose_h_kernel<float><<<dim3(Vv/32, Dm/32, 1), tb>>>(Wp, wpt, Dm, Vv);

    // transpose V per head: [H][T][E] -> [H][E][T]
    transpose_h_kernel<__half><<<dim3(Em/32, Tt/32, Hh), tb>>>(gv, gvT, Tt, Em);

    // 3) scores = Q K^T / sqrt(S): z = b*H + h
    size_t qO = (size_t)Ss*Em, qI = (size_t)Tt*Em;
    gemm_h<0,1>(gq,gk,nullptr,gsc, Ss,Ss,Em, Em,Em,Ss, Bb*Hh,Hh,
            qO,qI, qO,qI, (size_t)Hh*Ss*Ss,(size_t)Ss*Ss, 0,0,
            0.04419417382415922f);

    // 4) softmax (+mask)
    attn_softmax_kernel<<<Bb*Hh*Ss,128>>>(gsc, mask);

    // 5) ctx = attn @ V: B = Vt [H][E][T]
    gemm_h<0,1>(gsc,gvT,nullptr,gctx, Ss,Em,Ss, Ss,Tt,Hh*Em, Bb*Hh,Hh,
            (size_t)Hh*Ss*Ss,(size_t)Ss*Ss, (size_t)Ss,(size_t)Em*Tt,
            (size_t)Ss*Hh*Em,(size_t)Em, 0,0, 1.f);

    // 6) attn output proj (fp32 out) + LN (half out)
    gemm_h<0,0>(gctx,wot,bo,gf1, Tt,Dm,Hh*Em, Hh*Em,Hh*Em,Dm, 1,1,
            0,0, 0,0, 0,0, 0,0, 1.f);
    ln_kernel<<<Tt,256>>>(gf1, lng_a, lnb_a, gh2);

    // 7) FFN: gelu half out, then W2 fp32 out, LN half out
    gemm_h<1,1>(gh2,w1t,b1,gh1, Tt,Em,Dm, Dm,Dm,Em, 1,1, 0,0,0,0,0,0,0,0, 1.f);
    gemm_h<0,0>(gh1,w2t,b2,gf1, Tt,Dm,Em, Em,Em,Dm, 1,1, 0,0,0,0,0,0,0,0, 1.f);
    ln_kernel<<<Tt,256>>>(gf1, lng_f, lnb_f, genc);

    // 8) vocab logits (fp16 staging) -> log-softmax writes fp32 out
    gemm_h<0,1>(genc,wpt,bp,glog, Tt,Vv,Dm, Dm,Dm,Vv, 1,1, 0,0,0,0,0,0,0,0, 1.f);
    logsoftmax_h_kernel<<<Tt,512>>>(glog, out);

    // 9) cls head
    cls_kernel<<<8,128>>>(genc, Wc, bc, out);
}

// round 15
// speedup vs baseline: 1.1710x; 1.0933x over previous
#include <cuda_runtime.h>
#include <cuda_fp16.h>
#include <math.h>
#include <stdint.h>

#define F_INF __int_as_float(0x7f800000)

// Problem dims
#define Dm 768
#define Em 768
#define Hh 12
#define Bb 4
#define Ss 512
#define Vv 32000
#define Tt (Bb*Ss)   // 2048

// ---------------- scratch (device globals) ----------------------------------
__device__ __half g_x[Tt*Dm];              // embed+LN out
__device__ __half g_qkv[3*Hh*Tt*Em];       // [3][H][T][E]  (q,k,v slabs)
__device__ __half g_vT[Hh*Em*Tt];          // V transposed per head: [H][E][T]
__device__ __half g_sc[Bb*Hh*Ss*Ss];       // scores / attn
__device__ __half g_ctx[Tt*Hh*Em];
__device__ __half g_h1[Tt*Em];             // gelu intermediate
__device__ __half g_h2[Tt*Dm];             // LN(attn) out
__device__ __half g_enc[Tt*Dm];            // final LN out
__device__ float  g_f1[Tt*Dm];             // fp32 staging for LN inputs
__device__ __half g_logits[(size_t)Tt*Vv]; // fp16 logits staging
// packed transposed half weights
__device__ __half g_wqkvt[3*Hh*Em*Dm];     // [3][H][E][D]
__device__ float  g_bqkv[3*Hh*Em];         // packed fp32 biases
__device__ __half g_wot[Dm*Hh*Em];
__device__ __half g_w1t[Em*Dm];
__device__ __half g_w2t[Dm*Em];
__device__ __half g_wpt[Vv*Dm];

// ---------------- helpers ----------------
__device__ __forceinline__ float warpSum(float v){
    #pragma unroll
    for (int o=16;o;o>>=1) v += __shfl_xor_sync(0xffffffffu, v, o);
    return v;
}
__device__ __forceinline__ float warpMax(float v){
    #pragma unroll
    for (int o=16;o;o>>=1) v = fmaxf(v, __shfl_xor_sync(0xffffffffu, v, o));
    return v;
}
__device__ float blockSum(float v){
    __shared__ float sh[33];
    int lane = threadIdx.x & 31, wid = threadIdx.x >> 5;
    v = warpSum(v);
    __syncthreads();
    if (lane==0) sh[wid] = v;
    __syncthreads();
    if (wid==0){
        int nw = blockDim.x >> 5;
        float t = (lane < nw) ? sh[lane] : 0.f;
        t = warpSum(t);
        if (lane==0) sh[32] = t;
    }
    __syncthreads();
    return sh[32];
}
__device__ float blockMax(float v){
    __shared__ float sh[33];
    int lane = threadIdx.x & 31, wid = threadIdx.x >> 5;
    v = warpMax(v);
    __syncthreads();
    if (lane==0) sh[wid] = v;
    __syncthreads();
    if (wid==0){
        int nw = blockDim.x >> 5;
        float t = (lane < nw) ? sh[lane] : -F_INF;
        t = warpMax(t);
        if (lane==0) sh[32] = t;
    }
    __syncthreads();
    return sh[32];
}

// ---------------- transpose: src[R][C] -> dst[C][R] (to half) ---------------
template<typename TI>
__global__ void transpose_h_kernel(const TI* __restrict__ src,
                                   __half* __restrict__ dst,
                                   int R, int C)
{
    __shared__ float tile[32][33];
    int z = blockIdx.z;
    src += (size_t)z*R*C;
    dst += (size_t)z*R*C;
    int c0 = blockIdx.x*32, r0 = blockIdx.y*32;
    int tx = threadIdx.x, ty = threadIdx.y;     // 32 x 8
    #pragma unroll
    for (int i=0;i<32;i+=8)
        tile[ty+i][tx] = (float)src[(size_t)(r0+ty+i)*C + c0+tx];
    __syncthreads();
    #pragma unroll
    for (int i=0;i<32;i+=8)
        dst[(size_t)(c0+ty+i)*R + r0+tx] = __float2half(tile[tx][ty+i]);
}

// ---- fused 3-way transpose for Wq/Wk/Wv: z in [0,36), sel=z/12, head=z%12 ---
__global__ void transpose3_h_kernel(const float* __restrict__ Wq,
                                    const float* __restrict__ Wk,
                                    const float* __restrict__ Wv,
                                    __half* __restrict__ dst)
{
    __shared__ float tile[32][33];
    int z = blockIdx.z;
    int sel = z / Hh, zh = z % Hh;
    const float* src = (sel==0 ? Wq : (sel==1 ? Wk : Wv)) + (size_t)zh*Dm*Em;
    __half* d = dst + ((size_t)sel*Hh + zh)*(size_t)Em*Dm;
    int c0 = blockIdx.x*32, r0 = blockIdx.y*32;
    int tx = threadIdx.x, ty = threadIdx.y;     // 32 x 8
    #pragma unroll
    for (int i=0;i<32;i+=8)
        tile[ty+i][tx] = src[(size_t)(r0+ty+i)*Em + c0+tx];
    __syncthreads();
    #pragma unroll
    for (int i=0;i<32;i+=8)
        d[(size_t)(c0+ty+i)*Dm + r0+tx] = __float2half(tile[tx][ty+i]);
}

// ---------------- pack 3 bias arrays -----------------------------------------
__global__ void pack_bias_kernel(const float* __restrict__ bq,
                                 const float* __restrict__ bk,
                                 const float* __restrict__ bv,
                                 float* __restrict__ dst)
{
    int i = blockIdx.x*256 + threadIdx.x;
    if (i < Hh*Em){
        dst[i]            = bq[i];
        dst[Hh*Em + i]    = bk[i];
        dst[2*Hh*Em + i]  = bv[i];
    }
}

// ---------------- embedding + LayerNorm (half out) --------------------------
__global__ void embed_ln_kernel(const int* __restrict__ ids,
                                const float* __restrict__ tok,
                                const float* __restrict__ seg,
                                const float* __restrict__ gamma,
                                const float* __restrict__ beta,
                                __half* __restrict__ out)
{
    int t = blockIdx.x;
    int s = t % Ss;
    int id = ids[t];
    int sg = (s >= Ss/2 + 1) ? 1 : 0;
    int tid = threadIdx.x;
    float v[3];
    float lsum = 0.f, lsq = 0.f;
    #pragma unroll
    for (int r=0; r<3; r++){
        int i = tid + r*256;
        double di  = (2.0 * (double)i) / 768.0;
        double ang = (double)s * exp(-di * 9.210340371976184);
        float pos  = (i & 1) ? (float)cos(ang) : (float)sin(ang);
        float x = tok[(size_t)id*Dm + i] + seg[(size_t)sg*Dm + i] + pos;
        v[r] = x; lsum += x; lsq += x*x;
    }
    float sum = blockSum(lsum);
    float sq  = blockSum(lsq);
    float mean = sum * (1.f/Dm);
    float var  = sq * (1.f/Dm) - mean*mean;
    float inv  = rsqrtf(var + 1e-5f);
    #pragma unroll
    for (int r=0; r<3; r++){
        int i = tid + r*256;
        out[(size_t)t*Dm + i] = __float2half((v[r]-mean)*inv*gamma[i] + beta[i]);
    }
}

// ---------------- LayerNorm: fp32 in -> half out -----------------------------
__global__ void ln_kernel(const float* __restrict__ in,
                          const float* __restrict__ gamma,
                          const float* __restrict__ beta,
                          __half* __restrict__ out)
{
    int t = blockIdx.x;
    int tid = threadIdx.x;
    float v[3]; float lsum=0.f, lsq=0.f;
    #pragma unroll
    for (int r=0;r<3;r++){
        int i = tid + r*256;
        float x = in[(size_t)t*Dm + i];
        v[r]=x; lsum+=x; lsq+=x*x;
    }
    float sum = blockSum(lsum);
    float sq  = blockSum(lsq);
    float mean = sum * (1.f/Dm);
    float var  = sq * (1.f/Dm) - mean*mean;
    float inv  = rsqrtf(var + 1e-5f);
    #pragma unroll
    for (int r=0;r<3;r++){
        int i = tid + r*256;
        out[(size_t)t*Dm + i] = __float2half((v[r]-mean)*inv*gamma[i] + beta[i]);
    }
}

// ================= FP16 tensor-core GEMM, TB-only, cp.async 3-stage ==========
// C = act(alpha * A * B^T + bias). A [M][K] half, B [N][K] half.
// 128x128x64 block tile, 128 threads (4 warps 2x2), warp tile 64x64,
// m16n8k16 fp16 mma with fp32 accumulate. 12 k-iterations at K=768.
#define BM 128
#define BN 128
#define BKH 64                         // halves per k-tile
#define LROWH 72                       // halves per smem row (144B) -> conflict-free
#define TILE_BYTES (BM*LROWH*2)        // 18432
#define STAGE_BYTES (2*TILE_BYTES)     // 36864
#define NSTAGE 3
#define SMEM_BYTES  (NSTAGE*STAGE_BYTES)  // 110592

__device__ __forceinline__ void ldsm4(uint32_t& r0, uint32_t& r1, uint32_t& r2, uint32_t& r3, uint32_t addr){
    asm volatile("ldmatrix.sync.aligned.m8n8.x4.shared.b16 {%0,%1,%2,%3}, [%4];"
        : "=r"(r0),"=r"(r1),"=r"(r2),"=r"(r3) : "r"(addr));
}
__device__ __forceinline__ void mma_f16(float& c0,float& c1,float& c2,float& c3,
                                        uint32_t a0,uint32_t a1,uint32_t a2,uint32_t a3,
                                        uint32_t b0,uint32_t b1){
    asm volatile("mma.sync.aligned.m16n8k16.row.col.f32.f16.f16.f32 "
        "{%0,%1,%2,%3},{%4,%5,%6,%7},{%8,%9},{%0,%1,%2,%3};"
        : "+f"(c0),"+f"(c1),"+f"(c2),"+f"(c3)
        : "r"(a0),"r"(a1),"r"(a2),"r"(a3),"r"(b0),"r"(b1));
}
__device__ __forceinline__ void cp16(uint32_t dst, const __half* src){
    asm volatile("cp.async.cg.shared.global [%0], [%1], 16;" :: "r"(dst), "l"(src));
}

template<int ACT, int OUTHALF>
__global__ __launch_bounds__(128)
void hgemm_kernel(const __half* __restrict__ Ag, const __half* __restrict__ Bg,
                  const float* __restrict__ biasg, void* __restrict__ Cg,
                  int K, int lda, int ldb, int ldc,
                  int zdiv,
                  size_t sAo, size_t sAi, size_t sBo, size_t sBi,
                  size_t sCo, size_t sCi, size_t sbo, size_t sbi,
                  float alpha)
{
    extern __shared__ char dsm[];
    uint32_t s_base = (uint32_t)__cvta_generic_to_shared(dsm);

    int z  = blockIdx.z;
    int zo = z / zdiv, zi = z % zdiv;
    const __half* A = Ag + (size_t)zo*sAo + (size_t)zi*sAi;
    const __half* B = Bg + (size_t)zo*sBo + (size_t)zi*sBi;
    const float* bias = biasg ? (biasg + (size_t)zo*sbo + (size_t)zi*sbi) : nullptr;

    int m0 = blockIdx.x * BM;
    int n0 = blockIdx.y * BN;
    int tid = threadIdx.x, lane = tid & 31, warp = tid >> 5;
    int wm = warp & 1, wn = warp >> 1;      // warp tile (wm*64, wn*64)

    float acc[4][8][4];
    #pragma unroll
    for (int i=0;i<4;i++)
        #pragma unroll
        for (int j=0;j<8;j++)
            #pragma unroll
            for (int r=0;r<4;r++) acc[i][j][r]=0.f;

    // ldsm byte offsets relative to stage base
    int l15 = lane & 15, lhi = lane >> 4;
    uint32_t a_rel[4];
    #pragma unroll
    for (int i=0;i<4;i++)
        a_rel[i] = (uint32_t)(((wm*64 + i*16 + l15)*LROWH + 8*lhi)*2);
    int brow = (lane & 7) + ((lane & 16) ? 8 : 0);
    int bcol = (lane & 8) ? 8 : 0;   // halves
    uint32_t b_rel[4];
    #pragma unroll
    for (int jj=0;jj<4;jj++)
        b_rel[jj] = (uint32_t)(((wn*64 + jj*16 + brow)*LROWH + bcol)*2 + TILE_BYTES);

    int nk = K / BKH;
    auto load_stage = [&](int st, int kt){
        uint32_t sb = s_base + (uint32_t)st*STAGE_BYTES;
        int k0 = kt*BKH;
        // per tile: 128 rows x 8 chunks(16B) = 1024 chunks, 128 thr -> 8 iters
        #pragma unroll
        for (int it=0;it<8;it++){
            int c = tid + 128*it;
            int row = c >> 3, ch = c & 7;
            cp16(sb + (uint32_t)(row*144 + ch*16),
                 A + (size_t)(m0+row)*lda + k0 + ch*8);
        }
        #pragma unroll
        for (int it=0;it<8;it++){
            int c = tid + 128*it;
            int row = c >> 3, ch = c & 7;
            cp16(sb + (uint32_t)(TILE_BYTES + row*144 + ch*16),
                 B + (size_t)(n0+row)*ldb + k0 + ch*8);
        }
        asm volatile("cp.async.commit_group;");
    };

    load_stage(0, 0);
    load_stage(1, 1);

    uint32_t a[2][4][4], bf[2][8][2];
    int st = 0;
    for (int i=0; i<nk; i++){
        asm volatile("cp.async.wait_group 1;");
        __syncthreads();
        if (i+2 < nk) load_stage((st+2)%3, i+2);
        else asm volatile("cp.async.commit_group;");

        uint32_t abase = s_base + (uint32_t)st*STAGE_BYTES;
        // prefetch fragments for kk=0
        #pragma unroll
        for (int ii=0;ii<4;ii++)
            ldsm4(a[0][ii][0],a[0][ii][1],a[0][ii][2],a[0][ii][3], abase + a_rel[ii]);
        #pragma unroll
        for (int jj=0;jj<4;jj++)
            ldsm4(bf[0][2*jj][0],bf[0][2*jj][1],bf[0][2*jj+1][0],bf[0][2*jj+1][1], abase + b_rel[jj]);

        #pragma unroll
        for (int kk=0; kk<4; kk++){          // four k16 steps of the 64-k tile
            int cur = kk & 1, nxt = cur^1;
            if (kk+1 < 4){
                #pragma unroll
                for (int ii=0;ii<4;ii++)
                    ldsm4(a[nxt][ii][0],a[nxt][ii][1],a[nxt][ii][2],a[nxt][ii][3],
                          abase + a_rel[ii] + (kk+1)*32);
                #pragma unroll
                for (int jj=0;jj<4;jj++)
                    ldsm4(bf[nxt][2*jj][0],bf[nxt][2*jj][1],bf[nxt][2*jj+1][0],bf[nxt][2*jj+1][1],
                          abase + b_rel[jj] + (kk+1)*32);
            }
            #pragma unroll
            for (int ii=0;ii<4;ii++)
                #pragma unroll
                for (int jj=0;jj<8;jj++)
                    mma_f16(acc[ii][jj][0],acc[ii][jj][1],acc[ii][jj][2],acc[ii][jj][3],
                            a[cur][ii][0],a[cur][ii][1],a[cur][ii][2],a[cur][ii][3],
                            bf[cur][jj][0],bf[cur][jj][1]);
        }
        st = (st+1)%3;
    }

    // epilogue
    int g = lane >> 2, tg = lane & 3;
    #pragma unroll
    for (int i=0;i<4;i++){
        #pragma unroll
        for (int j=0;j<8;j++){
            int ncol = n0 + wn*64 + j*8 + 2*tg;
            float b0v = bias ? __ldg(&bias[ncol])   : 0.f;
            float b1v = bias ? __ldg(&bias[ncol+1]) : 0.f;
            #pragma unroll
            for (int h=0;h<2;h++){
                int mrow = m0 + wm*64 + i*16 + g + h*8;
                float v0 = acc[i][j][2*h+0]*alpha + b0v;
                float v1 = acc[i][j][2*h+1]*alpha + b1v;
                if (ACT==1){
                    v0 = 0.5f*v0*(1.0f + erff(v0*0.7071067811865475f));
                    v1 = 0.5f*v1*(1.0f + erff(v1*0.7071067811865475f));
                }
                size_t coff = (size_t)zo*sCo + (size_t)zi*sCi + (size_t)mrow*ldc + ncol;
                if (OUTHALF){
                    __half2* cp = (__half2*)((__half*)Cg + coff);
                    *cp = __floats2half2_rn(v0, v1);
                } else {
                    float2 o; o.x=v0; o.y=v1;
                    *(float2*)((float*)Cg + coff) = o;
                }
            }
        }
    }
}

// ---------------- attention softmax (half in/out) ---------------
__global__ void attn_softmax_kernel(__half* __restrict__ sc,
                                    const unsigned char* __restrict__ mask)
{
    int r = blockIdx.x;
    int z = r / Ss;
    int s = r % Ss;
    int b = z / Hh;
    __half* row = sc + (size_t)r * Ss;
    const unsigned char* mrow = mask + ((size_t)b*Ss + s)*Ss;
    int tid = threadIdx.x;
    float v[4]; float mx = -F_INF;
    #pragma unroll
    for (int rr=0;rr<4;rr++){
        int t = tid + rr*128;
        float x = __half2float(row[t]);
        if (mrow[t]) x = -1e9f;
        v[rr] = x; mx = fmaxf(mx, x);
    }
    mx = blockMax(mx);
    float ls = 0.f;
    #pragma unroll
    for (int rr=0;rr<4;rr++){ v[rr] = __expf(v[rr]-mx); ls += v[rr]; }
    float sum = blockSum(ls);
    float inv = 1.f/sum;
    #pragma unroll
    for (int rr=0;rr<4;rr++){
        int t = tid + rr*128;
        row[t] = __float2half(v[rr]*inv);
    }
}

// ---------------- log-softmax over vocab: half logits -> fp32 out ------------
__global__ __launch_bounds__(512) void logsoftmax_h_kernel(const __half* __restrict__ logits,
                                                           float* __restrict__ out)
{
    const int NV2 = Vv/2;   // 16000 half2 per row
    int t = blockIdx.x;
    const __half2* row = (const __half2*)(logits + (size_t)t * Vv);
    float2* orow = (float2*)(out + (size_t)t * Vv);
    int tid = threadIdx.x;
    __half2 v[32];
    float mx = -F_INF;
    #pragma unroll
    for (int k=0;k<32;k++){
        int i = tid + k*512;
        if (i < NV2){
            v[k] = row[i];
            float2 f = __half22float2(v[k]);
            mx = fmaxf(mx, fmaxf(f.x, f.y));
        }
    }
    mx = blockMax(mx);
    float ls = 0.f;
    #pragma unroll
    for (int k=0;k<32;k++){
        int i = tid + k*512;
        if (i < NV2){
            float2 f = __half22float2(v[k]);
            ls += __expf(f.x-mx) + __expf(f.y-mx);
        }
    }
    float sum = blockSum(ls);
    float sub = mx + logf(sum);
    #pragma unroll
    for (int k=0;k<32;k++){
        int i = tid + k*512;
        if (i < NV2){
            float2 f = __half22float2(v[k]);
            float2 o; o.x = f.x - sub; o.y = f.y - sub;
            orow[i] = o;
        }
    }
}

// ---------------- cls head (half enc) ----------------------------
__global__ void cls_kernel(const __half* __restrict__ enc,
                           const float* __restrict__ Wc,
                           const float* __restrict__ bc,
                           float* __restrict__ out)
{
    int b = blockIdx.x >> 1, c = blockIdx.x & 1;
    const __half* row = enc + (size_t)b*Ss*Dm;
    float lsum = 0.f;
    for (int i=threadIdx.x; i<Dm; i+=128)
        lsum += __half2float(row[i]) * Wc[(size_t)i*2 + c];
    float sum = blockSum(lsum);
    if (threadIdx.x==0)
        out[(size_t)Tt*Vv + b*2 + c] = sum + bc[c];
}

// ---------------- host launcher ---------------------------------------------
template<int ACT, int OUTHALF>
static inline void gemm_h(const __half* A, const __half* B, const float* bias, void* C,
                          int M,int N,int K,int lda,int ldb,int ldc,
                          int gz, int zdiv,
                          size_t sAo,size_t sAi,size_t sBo,size_t sBi,
                          size_t sCo,size_t sCi,size_t sbo,size_t sbi,
                          float alpha)
{
    cudaFuncSetAttribute(hgemm_kernel<ACT,OUTHALF>,
                         cudaFuncAttributeMaxDynamicSharedMemorySize, SMEM_BYTES);
    dim3 grid(M/BM, N/BN, gz), blk(128);
    hgemm_kernel<ACT,OUTHALF><<<grid,blk,SMEM_BYTES>>>(A,B,bias,C,K,lda,ldb,ldc,zdiv,
        sAo,sAi,sBo,sBi,sCo,sCi,sbo,sbi,alpha);
}

extern "C" void kernel_launch(void* const* d_in, const int* in_sizes, int n_in,
                              void* d_out, int out_size)
{
    (void)in_sizes; (void)n_in; (void)out_size;
    const int*   ids   = (const int*)  d_in[0];
    const unsigned char* mask = (const unsigned char*)d_in[1];
    const float* tok   = (const float*)d_in[2];
    const float* seg   = (const float*)d_in[3];
    const float* lng_e = (const float*)d_in[4];
    const float* lnb_e = (const float*)d_in[5];
    const float* Wq    = (const float*)d_in[6];
    const float* bq    = (const float*)d_in[7];
    const float* Wk    = (const float*)d_in[8];
    const float* bk    = (const float*)d_in[9];
    const float* Wv    = (const float*)d_in[10];
    const float* bv    = (const float*)d_in[11];
    const float* Wo    = (const float*)d_in[12];
    const float* bo    = (const float*)d_in[13];
    const float* lng_a = (const float*)d_in[14];
    const float* lnb_a = (const float*)d_in[15];
    const float* W1    = (const float*)d_in[16];
    const float* b1    = (const float*)d_in[17];
    const float* W2    = (const float*)d_in[18];
    const float* b2    = (const float*)d_in[19];
    const float* lng_f = (const float*)d_in[20];
    const float* lnb_f = (const float*)d_in[21];
    const float* Wp    = (const float*)d_in[22];
    const float* bp    = (const float*)d_in[23];
    const float* Wc    = (const float*)d_in[24];
    const float* bc    = (const float*)d_in[25];
    float* out = (float*)d_out;

    __half *gx,*gqkv,*gvT,*gsc,*gctx,*gh1,*gh2,*genc,*glog;
    __half *wqkvt,*wot,*w1t,*w2t,*wpt;
    float *gf1,*bqkv;
    cudaGetSymbolAddress((void**)&gx,   g_x);
    cudaGetSymbolAddress((void**)&gqkv, g_qkv);
    cudaGetSymbolAddress((void**)&gvT,  g_vT);
    cudaGetSymbolAddress((void**)&gsc,  g_sc);
    cudaGetSymbolAddress((void**)&gctx, g_ctx);
    cudaGetSymbolAddress((void**)&gh1,  g_h1);
    cudaGetSymbolAddress((void**)&gh2,  g_h2);
    cudaGetSymbolAddress((void**)&genc, g_enc);
    cudaGetSymbolAddress((void**)&gf1,  g_f1);
    cudaGetSymbolAddress((void**)&glog, g_logits);
    cudaGetSymbolAddress((void**)&wqkvt,g_wqkvt);
    cudaGetSymbolAddress((void**)&bqkv, g_bqkv);
    cudaGetSymbolAddress((void**)&wot,  g_wot);
    cudaGetSymbolAddress((void**)&w1t,  g_w1t);
    cudaGetSymbolAddress((void**)&w2t,  g_w2t);
    cudaGetSymbolAddress((void**)&wpt,  g_wpt);

    __half* gq = gqkv;
    __half* gk = gqkv + (size_t)Hh*Tt*Em;
    __half* gv = gqkv + 2*(size_t)Hh*Tt*Em;

    dim3 tb(32,8);
    // launch 0: fused QKV weight transpose; 1: bias pack; 2: embedding
    transpose3_h_kernel<<<dim3(Em/32, Dm/32, 3*Hh), tb>>>(Wq, Wk, Wv, wqkvt);     // 0
    pack_bias_kernel<<<(Hh*Em+255)/256,256>>>(bq, bk, bv, bqkv);                  // 1
    embed_ln_kernel<<<Tt,256>>>(ids, tok, seg, lng_e, lnb_e, gx);                 // 2

    // launch 3: fused QKV GEMM (captured by ncu)
    size_t sW = (size_t)Em*Dm, sC = (size_t)Tt*Em;
    gemm_h<0,1>(gx,wqkvt,bqkv,gqkv, Tt,Em,Dm, Dm,Dm,Em, 3*Hh,1,
                0,0, sW,0, sC,0, Em,0, 1.f);

    // deferred weight transposes (needed later)
    transpose_h_kernel<float><<<dim3(Dm/32, (Hh*Em)/32, 1), tb>>>(Wo, wot, Hh*Em, Dm);
    transpose_h_kernel<float><<<dim3(Em/32, Dm/32, 1), tb>>>(W1, w1t, Dm, Em);
    transpose_h_kernel<float><<<dim3(Dm/32, Em/32, 1), tb>>>(W2, w2t, Em, Dm);
    transpose_h_kernel<float><<<dim3(Vv/32, Dm/32, 1), tb>>>(Wp, wpt, Dm, Vv);

    // transpose V per head: [H][T][E] -> [H][E][T]
    transpose_h_kernel<__half><<<dim3(Em/32, Tt/32, Hh), tb>>>(gv, gvT, Tt, Em);

    // 3) scores = Q K^T / sqrt(S): z = b*H + h
    size_t qO = (size_t)Ss*Em, qI = (size_t)Tt*Em;
    gemm_h<0,1>(gq,gk,nullptr,gsc, Ss,Ss,Em, Em,Em,Ss, Bb*Hh,Hh,
            qO,qI, qO,qI, (size_t)Hh*Ss*Ss,(size_t)Ss*Ss, 0,0,
            0.04419417382415922f);

    // 4) softmax (+mask)
    attn_softmax_kernel<<<Bb*Hh*Ss,128>>>(gsc, mask);

    // 5) ctx = attn @ V: B = Vt [H][E][T]
    gemm_h<0,1>(gsc,gvT,nullptr,gctx, Ss,Em,Ss, Ss,Tt,Hh*Em, Bb*Hh,Hh,
            (size_t)Hh*Ss*Ss,(size_t)Ss*Ss, (size_t)Ss,(size_t)Em*Tt,
            (size_t)Ss*Hh*Em,(size_t)Em, 0,0, 1.f);

    // 6) attn output proj (fp32 out) + LN (half out)
    gemm_h<0,0>(gctx,wot,bo,gf1, Tt,Dm,Hh*Em, Hh*Em,Hh*Em,Dm, 1,1,
            0,0, 0,0, 0,0, 0,0, 1.f);
    ln_kernel<<<Tt,256>>>(gf1, lng_a, lnb_a, gh2);

    // 7) FFN: gelu half out, then W2 fp32 out, LN half out
    gemm_h<1,1>(gh2,w1t,b1,gh1, Tt,Em,Dm, Dm,Dm,Em, 1,1, 0,0,0,0,0,0,0,0, 1.f);
    gemm_h<0,0>(gh1,w2t,b2,gf1, Tt,Dm,Em, Em,Em,Dm, 1,1, 0,0,0,0,0,0,0,0, 1.f);
    ln_kernel<<<Tt,256>>>(gf1, lng_f, lnb_f, genc);

    // 8) vocab logits (fp16 staging) -> log-softmax writes fp32 out
    gemm_h<0,1>(genc,wpt,bp,glog, Tt,Vv,Dm, Dm,Dm,Vv, 1,1, 0,0,0,0,0,0,0,0, 1.f);
    logsoftmax_h_kernel<<<Tt,512>>>(glog, out);

    // 9) cls head
    cls_kernel<<<8,128>>>(genc, Wc, bc, out);
}

// round 17
// speedup vs baseline: 1.2061x; 1.0300x over previous
#include <cuda_runtime.h>
#include <cuda_fp16.h>
#include <math.h>
#include <stdint.h>

#define F_INF __int_as_float(0x7f800000)

// Problem dims
#define Dm 768
#define Em 768
#define Hh 12
#define Bb 4
#define Ss 512
#define Vv 32000
#define Tt (Bb*Ss)   // 2048

// ---------------- scratch (device globals) ----------------------------------
__device__ __half g_x[Tt*Dm];              // embed+LN out
__device__ __half g_qkv[3*Hh*Tt*Em];       // [3][H][T][E]  (q,k,v slabs)
__device__ __half g_vT[Hh*Em*Tt];          // V transposed per head: [H][E][T]
__device__ __half g_sc[Bb*Hh*Ss*Ss];       // scores / attn
__device__ __half g_ctx[Tt*Hh*Em];
__device__ __half g_h1[Tt*Em];             // gelu intermediate
__device__ __half g_h2[Tt*Dm];             // LN(attn) out
__device__ __half g_enc[Tt*Dm];            // final LN out
__device__ float  g_f1[Tt*Dm];             // fp32 staging for LN inputs
__device__ __half g_logits[(size_t)Tt*Vv]; // fp16 logits staging
// packed transposed half weights
__device__ __half g_wqkvt[3*Hh*Em*Dm];     // [3][H][E][D]
__device__ float  g_bqkv[3*Hh*Em];         // packed fp32 biases
__device__ __half g_wot[Dm*Hh*Em];
__device__ __half g_w1t[Em*Dm];
__device__ __half g_w2t[Dm*Em];
__device__ __half g_wpt[Vv*Dm];

// ---------------- helpers ----------------
__device__ __forceinline__ float warpSum(float v){
    #pragma unroll
    for (int o=16;o;o>>=1) v += __shfl_xor_sync(0xffffffffu, v, o);
    return v;
}
__device__ __forceinline__ float warpMax(float v){
    #pragma unroll
    for (int o=16;o;o>>=1) v = fmaxf(v, __shfl_xor_sync(0xffffffffu, v, o));
    return v;
}
__device__ float blockSum(float v){
    __shared__ float sh[33];
    int lane = threadIdx.x & 31, wid = threadIdx.x >> 5;
    v = warpSum(v);
    __syncthreads();
    if (lane==0) sh[wid] = v;
    __syncthreads();
    if (wid==0){
        int nw = blockDim.x >> 5;
        float t = (lane < nw) ? sh[lane] : 0.f;
        t = warpSum(t);
        if (lane==0) sh[32] = t;
    }
    __syncthreads();
    return sh[32];
}
__device__ float blockMax(float v){
    __shared__ float sh[33];
    int lane = threadIdx.x & 31, wid = threadIdx.x >> 5;
    v = warpMax(v);
    __syncthreads();
    if (lane==0) sh[wid] = v;
    __syncthreads();
    if (wid==0){
        int nw = blockDim.x >> 5;
        float t = (lane < nw) ? sh[lane] : -F_INF;
        t = warpMax(t);
        if (lane==0) sh[32] = t;
    }
    __syncthreads();
    return sh[32];
}

// ---------------- transpose: src[R][C] -> dst[C][R] (to half) ---------------
template<typename TI>
__global__ void transpose_h_kernel(const TI* __restrict__ src,
                                   __half* __restrict__ dst,
                                   int R, int C)
{
    __shared__ float tile[32][33];
    int z = blockIdx.z;
    src += (size_t)z*R*C;
    dst += (size_t)z*R*C;
    int c0 = blockIdx.x*32, r0 = blockIdx.y*32;
    int tx = threadIdx.x, ty = threadIdx.y;     // 32 x 8
    #pragma unroll
    for (int i=0;i<32;i+=8)
        tile[ty+i][tx] = (float)src[(size_t)(r0+ty+i)*C + c0+tx];
    __syncthreads();
    #pragma unroll
    for (int i=0;i<32;i+=8)
        dst[(size_t)(c0+ty+i)*R + r0+tx] = __float2half(tile[tx][ty+i]);
}

// ---- fused 3-way transpose for Wq/Wk/Wv: z in [0,36), sel=z/12, head=z%12 ---
__global__ void transpose3_h_kernel(const float* __restrict__ Wq,
                                    const float* __restrict__ Wk,
                                    const float* __restrict__ Wv,
                                    __half* __restrict__ dst)
{
    __shared__ float tile[32][33];
    int z = blockIdx.z;
    int sel = z / Hh, zh = z % Hh;
    const float* src = (sel==0 ? Wq : (sel==1 ? Wk : Wv)) + (size_t)zh*Dm*Em;
    __half* d = dst + ((size_t)sel*Hh + zh)*(size_t)Em*Dm;
    int c0 = blockIdx.x*32, r0 = blockIdx.y*32;
    int tx = threadIdx.x, ty = threadIdx.y;     // 32 x 8
    #pragma unroll
    for (int i=0;i<32;i+=8)
        tile[ty+i][tx] = src[(size_t)(r0+ty+i)*Em + c0+tx];
    __syncthreads();
    #pragma unroll
    for (int i=0;i<32;i+=8)
        d[(size_t)(c0+ty+i)*Dm + r0+tx] = __float2half(tile[tx][ty+i]);
}

// ---------------- pack 3 bias arrays -----------------------------------------
__global__ void pack_bias_kernel(const float* __restrict__ bq,
                                 const float* __restrict__ bk,
                                 const float* __restrict__ bv,
                                 float* __restrict__ dst)
{
    int i = blockIdx.x*256 + threadIdx.x;
    if (i < Hh*Em){
        dst[i]            = bq[i];
        dst[Hh*Em + i]    = bk[i];
        dst[2*Hh*Em + i]  = bv[i];
    }
}

// ---------------- embedding + LayerNorm (half out) --------------------------
__global__ void embed_ln_kernel(const int* __restrict__ ids,
                                const float* __restrict__ tok,
                                const float* __restrict__ seg,
                                const float* __restrict__ gamma,
                                const float* __restrict__ beta,
                                __half* __restrict__ out)
{
    int t = blockIdx.x;
    int s = t % Ss;
    int id = ids[t];
    int sg = (s >= Ss/2 + 1) ? 1 : 0;
    int tid = threadIdx.x;
    float v[3];
    float lsum = 0.f, lsq = 0.f;
    #pragma unroll
    for (int r=0; r<3; r++){
        int i = tid + r*256;
        double di  = (2.0 * (double)i) / 768.0;
        double ang = (double)s * exp(-di * 9.210340371976184);
        float pos  = (i & 1) ? (float)cos(ang) : (float)sin(ang);
        float x = tok[(size_t)id*Dm + i] + seg[(size_t)sg*Dm + i] + pos;
        v[r] = x; lsum += x; lsq += x*x;
    }
    float sum = blockSum(lsum);
    float sq  = blockSum(lsq);
    float mean = sum * (1.f/Dm);
    float var  = sq * (1.f/Dm) - mean*mean;
    float inv  = rsqrtf(var + 1e-5f);
    #pragma unroll
    for (int r=0; r<3; r++){
        int i = tid + r*256;
        out[(size_t)t*Dm + i] = __float2half((v[r]-mean)*inv*gamma[i] + beta[i]);
    }
}

// ---------------- LayerNorm: fp32 in -> half out -----------------------------
__global__ void ln_kernel(const float* __restrict__ in,
                          const float* __restrict__ gamma,
                          const float* __restrict__ beta,
                          __half* __restrict__ out)
{
    int t = blockIdx.x;
    int tid = threadIdx.x;
    float v[3]; float lsum=0.f, lsq=0.f;
    #pragma unroll
    for (int r=0;r<3;r++){
        int i = tid + r*256;
        float x = in[(size_t)t*Dm + i];
        v[r]=x; lsum+=x; lsq+=x*x;
    }
    float sum = blockSum(lsum);
    float sq  = blockSum(lsq);
    float mean = sum * (1.f/Dm);
    float var  = sq * (1.f/Dm) - mean*mean;
    float inv  = rsqrtf(var + 1e-5f);
    #pragma unroll
    for (int r=0;r<3;r++){
        int i = tid + r*256;
        out[(size_t)t*Dm + i] = __float2half((v[r]-mean)*inv*gamma[i] + beta[i]);
    }
}

// ================= FP16 tensor-core GEMM, TB-only, cp.async 3-stage ==========
// C = act(alpha * A * B^T + bias). A [M][K] half, B [N][K] half.
// 128x128x64 block tile, 128 threads (4 warps 2x2), warp tile 64x64.
#define BM 128
#define BN 128
#define BKH 64                         // halves per k-tile
#define LROWH 72                       // halves per smem row (144B) -> conflict-free
#define TILE_BYTES (BM*LROWH*2)        // 18432
#define STAGE_BYTES (2*TILE_BYTES)     // 36864
#define NSTAGE 3
#define SMEM_BYTES  (NSTAGE*STAGE_BYTES)  // 110592

__device__ __forceinline__ void ldsm4(uint32_t& r0, uint32_t& r1, uint32_t& r2, uint32_t& r3, uint32_t addr){
    asm volatile("ldmatrix.sync.aligned.m8n8.x4.shared.b16 {%0,%1,%2,%3}, [%4];"
        : "=r"(r0),"=r"(r1),"=r"(r2),"=r"(r3) : "r"(addr));
}
__device__ __forceinline__ void mma_f16(float& c0,float& c1,float& c2,float& c3,
                                        uint32_t a0,uint32_t a1,uint32_t a2,uint32_t a3,
                                        uint32_t b0,uint32_t b1){
    asm volatile("mma.sync.aligned.m16n8k16.row.col.f32.f16.f16.f32 "
        "{%0,%1,%2,%3},{%4,%5,%6,%7},{%8,%9},{%0,%1,%2,%3};"
        : "+f"(c0),"+f"(c1),"+f"(c2),"+f"(c3)
        : "r"(a0),"r"(a1),"r"(a2),"r"(a3),"r"(b0),"r"(b1));
}
__device__ __forceinline__ void cp16(uint32_t dst, const __half* src){
    asm volatile("cp.async.cg.shared.global [%0], [%1], 16;" :: "r"(dst), "l"(src));
}

template<int ACT, int OUTHALF>
__global__ __launch_bounds__(128)
void hgemm_kernel(const __half* __restrict__ Ag, const __half* __restrict__ Bg,
                  const float* __restrict__ biasg, void* __restrict__ Cg,
                  int K, int lda, int ldb, int ldc,
                  int zdiv,
                  size_t sAo, size_t sAi, size_t sBo, size_t sBi,
                  size_t sCo, size_t sCi, size_t sbo, size_t sbi,
                  float alpha)
{
    extern __shared__ char dsm[];
    uint32_t s_base = (uint32_t)__cvta_generic_to_shared(dsm);

    int z  = blockIdx.z;
    int zo = z / zdiv, zi = z % zdiv;
    const __half* A = Ag + (size_t)zo*sAo + (size_t)zi*sAi;
    const __half* B = Bg + (size_t)zo*sBo + (size_t)zi*sBi;
    const float* bias = biasg ? (biasg + (size_t)zo*sbo + (size_t)zi*sbi) : nullptr;

    int m0 = blockIdx.x * BM;
    int n0 = blockIdx.y * BN;
    int tid = threadIdx.x, lane = tid & 31, warp = tid >> 5;
    int wm = warp & 1, wn = warp >> 1;      // warp tile (wm*64, wn*64)

    float acc[4][8][4];
    #pragma unroll
    for (int i=0;i<4;i++)
        #pragma unroll
        for (int j=0;j<8;j++)
            #pragma unroll
            for (int r=0;r<4;r++) acc[i][j][r]=0.f;

    // ldsm byte offsets relative to stage base
    int l15 = lane & 15, lhi = lane >> 4;
    uint32_t a_rel[4];
    #pragma unroll
    for (int i=0;i<4;i++)
        a_rel[i] = (uint32_t)(((wm*64 + i*16 + l15)*LROWH + 8*lhi)*2);
    int brow = (lane & 7) + ((lane & 16) ? 8 : 0);
    int bcol = (lane & 8) ? 8 : 0;   // halves
    uint32_t b_rel[4];
    #pragma unroll
    for (int jj=0;jj<4;jj++)
        b_rel[jj] = (uint32_t)(((wn*64 + jj*16 + brow)*LROWH + bcol)*2 + TILE_BYTES);

    int nk = K / BKH;
    auto load_stage = [&](int st, int kt){
        uint32_t sb = s_base + (uint32_t)st*STAGE_BYTES;
        int k0 = kt*BKH;
        #pragma unroll
        for (int it=0;it<8;it++){
            int c = tid + 128*it;
            int row = c >> 3, ch = c & 7;
            cp16(sb + (uint32_t)(row*144 + ch*16),
                 A + (size_t)(m0+row)*lda + k0 + ch*8);
        }
        #pragma unroll
        for (int it=0;it<8;it++){
            int c = tid + 128*it;
            int row = c >> 3, ch = c & 7;
            cp16(sb + (uint32_t)(TILE_BYTES + row*144 + ch*16),
                 B + (size_t)(n0+row)*ldb + k0 + ch*8);
        }
        asm volatile("cp.async.commit_group;");
    };

    load_stage(0, 0);
    load_stage(1, 1);

    uint32_t a[2][4][4], bf[2][8][2];
    int st = 0;
    for (int i=0; i<nk; i++){
        asm volatile("cp.async.wait_group 1;");
        __syncthreads();
        if (i+2 < nk) load_stage((st+2)%3, i+2);
        else asm volatile("cp.async.commit_group;");

        uint32_t abase = s_base + (uint32_t)st*STAGE_BYTES;
        // prefetch fragments for kk=0
        #pragma unroll
        for (int ii=0;ii<4;ii++)
            ldsm4(a[0][ii][0],a[0][ii][1],a[0][ii][2],a[0][ii][3], abase + a_rel[ii]);
        #pragma unroll
        for (int jj=0;jj<4;jj++)
            ldsm4(bf[0][2*jj][0],bf[0][2*jj][1],bf[0][2*jj+1][0],bf[0][2*jj+1][1], abase + b_rel[jj]);

        #pragma unroll
        for (int kk=0; kk<4; kk++){          // four k16 steps of the 64-k tile
            int cur = kk & 1, nxt = cur^1;
            if (kk+1 < 4){
                #pragma unroll
                for (int ii=0;ii<4;ii++)
                    ldsm4(a[nxt][ii][0],a[nxt][ii][1],a[nxt][ii][2],a[nxt][ii][3],
                          abase + a_rel[ii] + (kk+1)*32);
                #pragma unroll
                for (int jj=0;jj<4;jj++)
                    ldsm4(bf[nxt][2*jj][0],bf[nxt][2*jj][1],bf[nxt][2*jj+1][0],bf[nxt][2*jj+1][1],
                          abase + b_rel[jj] + (kk+1)*32);
            }
            #pragma unroll
            for (int ii=0;ii<4;ii++)
                #pragma unroll
                for (int jj=0;jj<8;jj++)
                    mma_f16(acc[ii][jj][0],acc[ii][jj][1],acc[ii][jj][2],acc[ii][jj][3],
                            a[cur][ii][0],a[cur][ii][1],a[cur][ii][2],a[cur][ii][3],
                            bf[cur][jj][0],bf[cur][jj][1]);
        }
        st = (st+1)%3;
    }

    // epilogue
    int g = lane >> 2, tg = lane & 3;
    #pragma unroll
    for (int i=0;i<4;i++){
        #pragma unroll
        for (int j=0;j<8;j++){
            int ncol = n0 + wn*64 + j*8 + 2*tg;
            float b0v = bias ? __ldg(&bias[ncol])   : 0.f;
            float b1v = bias ? __ldg(&bias[ncol+1]) : 0.f;
            #pragma unroll
            for (int h=0;h<2;h++){
                int mrow = m0 + wm*64 + i*16 + g + h*8;
                float v0 = acc[i][j][2*h+0]*alpha + b0v;
                float v1 = acc[i][j][2*h+1]*alpha + b1v;
                if (ACT==1){
                    v0 = 0.5f*v0*(1.0f + erff(v0*0.7071067811865475f));
                    v1 = 0.5f*v1*(1.0f + erff(v1*0.7071067811865475f));
                }
                size_t coff = (size_t)zo*sCo + (size_t)zi*sCi + (size_t)mrow*ldc + ncol;
                if (OUTHALF){
                    __half2* cp = (__half2*)((__half*)Cg + coff);
                    *cp = __floats2half2_rn(v0, v1);
                } else {
                    float2 o; o.x=v0; o.y=v1;
                    *(float2*)((float*)Cg + coff) = o;
                }
            }
        }
    }
}

// ---------------- attention softmax (half in/out) ---------------
__global__ void attn_softmax_kernel(__half* __restrict__ sc,
                                    const unsigned char* __restrict__ mask)
{
    int r = blockIdx.x;
    int z = r / Ss;
    int s = r % Ss;
    int b = z / Hh;
    __half* row = sc + (size_t)r * Ss;
    const unsigned char* mrow = mask + ((size_t)b*Ss + s)*Ss;
    int tid = threadIdx.x;
    float v[4]; float mx = -F_INF;
    #pragma unroll
    for (int rr=0;rr<4;rr++){
        int t = tid + rr*128;
        float x = __half2float(row[t]);
        if (mrow[t]) x = -1e9f;
        v[rr] = x; mx = fmaxf(mx, x);
    }
    mx = blockMax(mx);
    float ls = 0.f;
    #pragma unroll
    for (int rr=0;rr<4;rr++){ v[rr] = __expf(v[rr]-mx); ls += v[rr]; }
    float sum = blockSum(ls);
    float inv = 1.f/sum;
    #pragma unroll
    for (int rr=0;rr<4;rr++){
        int t = tid + rr*128;
        row[t] = __float2half(v[rr]*inv);
    }
}

// ---------------- log-softmax over vocab: half logits -> fp32 out ------------
__global__ __launch_bounds__(512) void logsoftmax_h_kernel(const __half* __restrict__ logits,
                                                           float* __restrict__ out)
{
    const int NV2 = Vv/2;   // 16000 half2 per row
    int t = blockIdx.x;
    const __half2* row = (const __half2*)(logits + (size_t)t * Vv);
    float2* orow = (float2*)(out + (size_t)t * Vv);
    int tid = threadIdx.x;
    __half2 v[32];
    float mx = -F_INF;
    #pragma unroll
    for (int k=0;k<32;k++){
        int i = tid + k*512;
        if (i < NV2){
            v[k] = row[i];
            float2 f = __half22float2(v[k]);
            mx = fmaxf(mx, fmaxf(f.x, f.y));
        }
    }
    mx = blockMax(mx);
    float ls = 0.f;
    #pragma unroll
    for (int k=0;k<32;k++){
        int i = tid + k*512;
        if (i < NV2){
            float2 f = __half22float2(v[k]);
            ls += __expf(f.x-mx) + __expf(f.y-mx);
        }
    }
    float sum = blockSum(ls);
    float sub = mx + logf(sum);
    #pragma unroll
    for (int k=0;k<32;k++){
        int i = tid + k*512;
        if (i < NV2){
            float2 f = __half22float2(v[k]);
            float2 o; o.x = f.x - sub; o.y = f.y - sub;
            orow[i] = o;
        }
    }
}

// ---------------- cls head (half enc) ----------------------------
__global__ void cls_kernel(const __half* __restrict__ enc,
                           const float* __restrict__ Wc,
                           const float* __restrict__ bc,
                           float* __restrict__ out)
{
    int b = blockIdx.x >> 1, c = blockIdx.x & 1;
    const __half* row = enc + (size_t)b*Ss*Dm;
    float lsum = 0.f;
    for (int i=threadIdx.x; i<Dm; i+=128)
        lsum += __half2float(row[i]) * Wc[(size_t)i*2 + c];
    float sum = blockSum(lsum);
    if (threadIdx.x==0)
        out[(size_t)Tt*Vv + b*2 + c] = sum + bc[c];
}

// ---------------- host launcher ---------------------------------------------
template<int ACT, int OUTHALF>
static inline void gemm_h(const __half* A, const __half* B, const float* bias, void* C,
                          int M,int N,int K,int lda,int ldb,int ldc,
                          int gz, int zdiv,
                          size_t sAo,size_t sAi,size_t sBo,size_t sBi,
                          size_t sCo,size_t sCi,size_t sbo,size_t sbi,
                          float alpha)
{
    cudaFuncSetAttribute(hgemm_kernel<ACT,OUTHALF>,
                         cudaFuncAttributeMaxDynamicSharedMemorySize, SMEM_BYTES);
    dim3 grid(M/BM, N/BN, gz), blk(128);
    hgemm_kernel<ACT,OUTHALF><<<grid,blk,SMEM_BYTES>>>(A,B,bias,C,K,lda,ldb,ldc,zdiv,
        sAo,sAi,sBo,sBi,sCo,sCi,sbo,sbi,alpha);
}

extern "C" void kernel_launch(void* const* d_in, const int* in_sizes, int n_in,
                              void* d_out, int out_size)
{
    (void)in_sizes; (void)n_in; (void)out_size;
    const int*   ids   = (const int*)  d_in[0];
    const unsigned char* mask = (const unsigned char*)d_in[1];
    const float* tok   = (const float*)d_in[2];
    const float* seg   = (const float*)d_in[3];
    const float* lng_e = (const float*)d_in[4];
    const float* lnb_e = (const float*)d_in[5];
    const float* Wq    = (const float*)d_in[6];
    const float* bq    = (const float*)d_in[7];
    const float* Wk    = (const float*)d_in[8];
    const float* bk    = (const float*)d_in[9];
    const float* Wv    = (const float*)d_in[10];
    const float* bv    = (const float*)d_in[11];
    const float* Wo    = (const float*)d_in[12];
    const float* bo    = (const float*)d_in[13];
    const float* lng_a = (const float*)d_in[14];
    const float* lnb_a = (const float*)d_in[15];
    const float* W1    = (const float*)d_in[16];
    const float* b1    = (const float*)d_in[17];
    const float* W2    = (const float*)d_in[18];
    const float* b2    = (const float*)d_in[19];
    const float* lng_f = (const float*)d_in[20];
    const float* lnb_f = (const float*)d_in[21];
    const float* Wp    = (const float*)d_in[22];
    const float* bp    = (const float*)d_in[23];
    const float* Wc    = (const float*)d_in[24];
    const float* bc    = (const float*)d_in[25];
    float* out = (float*)d_out;

    __half *gx,*gqkv,*gvT,*gsc,*gctx,*gh1,*gh2,*genc,*glog;
    __half *wqkvt,*wot,*w1t,*w2t,*wpt;
    float *gf1,*bqkv;
    cudaGetSymbolAddress((void**)&gx,   g_x);
    cudaGetSymbolAddress((void**)&gqkv, g_qkv);
    cudaGetSymbolAddress((void**)&gvT,  g_vT);
    cudaGetSymbolAddress((void**)&gsc,  g_sc);
    cudaGetSymbolAddress((void**)&gctx, g_ctx);
    cudaGetSymbolAddress((void**)&gh1,  g_h1);
    cudaGetSymbolAddress((void**)&gh2,  g_h2);
    cudaGetSymbolAddress((void**)&genc, g_enc);
    cudaGetSymbolAddress((void**)&gf1,  g_f1);
    cudaGetSymbolAddress((void**)&glog, g_logits);
    cudaGetSymbolAddress((void**)&wqkvt,g_wqkvt);
    cudaGetSymbolAddress((void**)&bqkv, g_bqkv);
    cudaGetSymbolAddress((void**)&wot,  g_wot);
    cudaGetSymbolAddress((void**)&w1t,  g_w1t);
    cudaGetSymbolAddress((void**)&w2t,  g_w2t);
    cudaGetSymbolAddress((void**)&wpt,  g_wpt);

    __half* gq = gqkv;
    __half* gk = gqkv + (size_t)Hh*Tt*Em;
    __half* gv = gqkv + 2*(size_t)Hh*Tt*Em;

    // side streams + fork/join events: created ONCE on the first call (the
    // correctness run, which precedes the harness's pre-capture memory
    // baseline). Capture-time calls allocate nothing.
    static cudaStream_t sWs = nullptr, sVs = nullptr;
    static cudaEvent_t evRoot = nullptr, evW = nullptr, evQKV = nullptr, evVT = nullptr;
    if (!sWs){
        cudaStreamCreateWithFlags(&sWs, cudaStreamNonBlocking);
        cudaStreamCreateWithFlags(&sVs, cudaStreamNonBlocking);
        cudaEventCreateWithFlags(&evRoot, cudaEventDisableTiming);
        cudaEventCreateWithFlags(&evW,    cudaEventDisableTiming);
        cudaEventCreateWithFlags(&evQKV,  cudaEventDisableTiming);
        cudaEventCreateWithFlags(&evVT,   cudaEventDisableTiming);
    }

    dim3 tb(32,8);

    // fork: deferred weight transposes run on side stream sWs
    cudaEventRecord(evRoot, 0);
    cudaStreamWaitEvent(sWs, evRoot, 0);
    transpose_h_kernel<float><<<dim3(Dm/32, (Hh*Em)/32, 1), tb, 0, sWs>>>(Wo, wot, Hh*Em, Dm);
    transpose_h_kernel<float><<<dim3(Em/32, Dm/32, 1), tb, 0, sWs>>>(W1, w1t, Dm, Em);
    transpose_h_kernel<float><<<dim3(Dm/32, Em/32, 1), tb, 0, sWs>>>(W2, w2t, Em, Dm);
    transpose_h_kernel<float><<<dim3(Vv/32, Dm/32, 1), tb, 0, sWs>>>(Wp, wpt, Dm, Vv);
    cudaEventRecord(evW, sWs);

    // main stream: QKV prep + GEMM
    transpose3_h_kernel<<<dim3(Em/32, Dm/32, 3*Hh), tb>>>(Wq, Wk, Wv, wqkvt);
    pack_bias_kernel<<<(Hh*Em+255)/256,256>>>(bq, bk, bv, bqkv);
    embed_ln_kernel<<<Tt,256>>>(ids, tok, seg, lng_e, lnb_e, gx);

    size_t sW = (size_t)Em*Dm, sC = (size_t)Tt*Em;
    gemm_h<0,1>(gx,wqkvt,bqkv,gqkv, Tt,Em,Dm, Dm,Dm,Em, 3*Hh,1,
                0,0, sW,0, sC,0, Em,0, 1.f);

    // fork: V transpose on side stream sVs (needs QKV output)
    cudaEventRecord(evQKV, 0);
    cudaStreamWaitEvent(sVs, evQKV, 0);
    transpose_h_kernel<__half><<<dim3(Em/32, Tt/32, Hh), tb, 0, sVs>>>(gv, gvT, Tt, Em);
    cudaEventRecord(evVT, sVs);

    // main: scores GEMM + softmax (independent of V transpose)
    size_t qO = (size_t)Ss*Em, qI = (size_t)Tt*Em;
    gemm_h<0,1>(gq,gk,nullptr,gsc, Ss,Ss,Em, Em,Em,Ss, Bb*Hh,Hh,
            qO,qI, qO,qI, (size_t)Hh*Ss*Ss,(size_t)Ss*Ss, 0,0,
            0.04419417382415922f);
    attn_softmax_kernel<<<Bb*Hh*Ss,128>>>(gsc, mask);

    // join: ctx GEMM needs gvT
    cudaStreamWaitEvent(0, evVT, 0);
    gemm_h<0,1>(gsc,gvT,nullptr,gctx, Ss,Em,Ss, Ss,Tt,Hh*Em, Bb*Hh,Hh,
            (size_t)Hh*Ss*Ss,(size_t)Ss*Ss, (size_t)Ss,(size_t)Em*Tt,
            (size_t)Ss*Hh*Em,(size_t)Em, 0,0, 1.f);

    // join: Wo/W1/W2/Wp transposes must be done before the projection chain
    cudaStreamWaitEvent(0, evW, 0);

    // 6) attn output proj (fp32 out) + LN (half out)
    gemm_h<0,0>(gctx,wot,bo,gf1, Tt,Dm,Hh*Em, Hh*Em,Hh*Em,Dm, 1,1,
            0,0, 0,0, 0,0, 0,0, 1.f);
    ln_kernel<<<Tt,256>>>(gf1, lng_a, lnb_a, gh2);

    // 7) FFN: gelu half out, then W2 fp32 out, LN half out
    gemm_h<1,1>(gh2,w1t,b1,gh1, Tt,Em,Dm, Dm,Dm,Em, 1,1, 0,0,0,0,0,0,0,0, 1.f);
    gemm_h<0,0>(gh1,w2t,b2,gf1, Tt,Dm,Em, Em,Em,Dm, 1,1, 0,0,0,0,0,0,0,0, 1.f);
    ln_kernel<<<Tt,256>>>(gf1, lng_f, lnb_f, genc);

    // 8) vocab logits (fp16 staging) -> log-softmax writes fp32 out
    gemm_h<0,1>(genc,wpt,bp,glog, Tt,Vv,Dm, Dm,Dm,Vv, 1,1, 0,0,0,0,0,0,0,0, 1.f);
    logsoftmax_h_kernel<<<Tt,512>>>(glog, out);

    // 9) cls head
    cls_kernel<<<8,128>>>(genc, Wc, bc, out);
}